// round 2
// baseline (speedup 1.0000x reference)
#include <cuda_runtime.h>
#include <cuda_bf16.h>

#define B_ 2
#define S_ 2048
#define DIN_ 2048
#define H_ 32
#define G_ 8
#define D_ 64
#define GS_ (H_ / G_)
#define HD_ (H_ * D_)
#define GD_ (G_ * D_)

// Scratch (static device globals; allocation APIs are forbidden)
__device__ float g_q_raw[B_ * S_ * HD_];   // [B*S, H*D]
__device__ float g_k_raw[B_ * S_ * GD_];   // [B*S, G*D]
__device__ float g_v_raw[B_ * S_ * GD_];   // [B*S, G*D]
__device__ float g_q_att[B_ * S_ * HD_];   // [B, H, S, D]
__device__ float g_ctx[B_ * S_ * HD_];     // [B, S, H*D]

// ---------------------------------------------------------------------------
// SGEMM: C[M,N] = A[M,K] @ B[K,N], row-major fp32.
// 128x128 tile, BK=8, 256 threads, 8x8 per thread.
// ---------------------------------------------------------------------------
#define BM 128
#define BN 128
#define BK 8

__global__ __launch_bounds__(256) void sgemm_kernel(
    const float* __restrict__ A, const float* __restrict__ Bm,
    float* __restrict__ C, int M, int N, int K)
{
    __shared__ float As[BK][BM + 4];  // transposed: As[k][m]
    __shared__ float Bs[BK][BN];      // Bs[k][n]

    int tid = threadIdx.x;
    int tx = tid & 15;        // 0..15
    int ty = tid >> 4;        // 0..15
    int rowBase = blockIdx.y * BM;
    int colBase = blockIdx.x * BN;

    // Global load mapping
    int aRow  = tid >> 1;          // 0..127
    int aColV = (tid & 1) * 4;     // 0 or 4
    int bRow  = tid >> 5;          // 0..7
    int bColV = (tid & 31) * 4;    // 0..124

    const float* Aptr = A + (size_t)(rowBase + aRow) * K + aColV;
    const float* Bptr = Bm + (size_t)bRow * N + colBase + bColV;

    float acc[8][8];
#pragma unroll
    for (int i = 0; i < 8; i++)
#pragma unroll
        for (int j = 0; j < 8; j++) acc[i][j] = 0.f;

    for (int k0 = 0; k0 < K; k0 += BK) {
        float4 av = *(const float4*)(Aptr + k0);
        float4 bv = *(const float4*)(Bptr + (size_t)k0 * N);
        As[aColV + 0][aRow] = av.x;
        As[aColV + 1][aRow] = av.y;
        As[aColV + 2][aRow] = av.z;
        As[aColV + 3][aRow] = av.w;
        *(float4*)&Bs[bRow][bColV] = bv;
        __syncthreads();

#pragma unroll
        for (int kk = 0; kk < BK; kk++) {
            float ar[8], br[8];
            float4 a0 = *(const float4*)&As[kk][ty * 8 + 0];
            float4 a1 = *(const float4*)&As[kk][ty * 8 + 4];
            float4 b0 = *(const float4*)&Bs[kk][tx * 8 + 0];
            float4 b1 = *(const float4*)&Bs[kk][tx * 8 + 4];
            ar[0] = a0.x; ar[1] = a0.y; ar[2] = a0.z; ar[3] = a0.w;
            ar[4] = a1.x; ar[5] = a1.y; ar[6] = a1.z; ar[7] = a1.w;
            br[0] = b0.x; br[1] = b0.y; br[2] = b0.z; br[3] = b0.w;
            br[4] = b1.x; br[5] = b1.y; br[6] = b1.z; br[7] = b1.w;
#pragma unroll
            for (int i = 0; i < 8; i++)
#pragma unroll
                for (int j = 0; j < 8; j++) acc[i][j] += ar[i] * br[j];
        }
        __syncthreads();
    }

#pragma unroll
    for (int i = 0; i < 8; i++) {
        int row = rowBase + ty * 8 + i;
        float4 v0 = make_float4(acc[i][0], acc[i][1], acc[i][2], acc[i][3]);
        float4 v1 = make_float4(acc[i][4], acc[i][5], acc[i][6], acc[i][7]);
        *(float4*)&C[(size_t)row * N + colBase + tx * 8 + 0] = v0;
        *(float4*)&C[(size_t)row * N + colBase + tx * 8 + 4] = v1;
    }
}

// ---------------------------------------------------------------------------
// RMSNorm + RoPE. One warp per (b,s,head). in: [B*S, NH*D]; out: [B, NH, S, D]
// lane l holds d=l and d=l+32 (conveniently the two rope halves).
// ---------------------------------------------------------------------------
__global__ void normrope_kernel(const float* __restrict__ in,
                                float* __restrict__ out,
                                const float* __restrict__ scale,
                                const float* __restrict__ cosp,
                                const float* __restrict__ sinp,
                                int NH)
{
    int w = (blockIdx.x * blockDim.x + threadIdx.x) >> 5;
    int lane = threadIdx.x & 31;
    int nh = w % NH;
    int bs = w / NH;          // b*S + s
    int s = bs % S_;
    int b = bs / S_;

    const float* row = in + (size_t)bs * NH * D_ + nh * D_;
    float x0 = row[lane];
    float x1 = row[lane + 32];
    float ss = x0 * x0 + x1 * x1;
#pragma unroll
    for (int o = 16; o > 0; o >>= 1) ss += __shfl_xor_sync(0xffffffffu, ss, o);
    float rinv = rsqrtf(ss * (1.0f / 64.0f) + 1e-6f);
    float n0 = x0 * rinv * scale[lane];
    float n1 = x1 * rinv * scale[lane + 32];

    float c0 = cosp[s * D_ + lane];
    float c1 = cosp[s * D_ + lane + 32];
    float s0 = sinp[s * D_ + lane];
    float s1 = sinp[s * D_ + lane + 32];
    // rotated = [-x2, x1]
    float r0 = n0 * c0 - n1 * s0;
    float r1 = n1 * c1 + n0 * s1;

    float* orow = out + (((size_t)b * NH + nh) * S_ + s) * D_;
    orow[lane] = r0;
    orow[lane + 32] = r1;
}

// ---------------------------------------------------------------------------
// V transpose: [b,s,g,d] -> [b,g,s,d]
// ---------------------------------------------------------------------------
__global__ void vtrans_kernel(const float* __restrict__ in, float* __restrict__ out)
{
    int i = blockIdx.x * blockDim.x + threadIdx.x;  // over B*S*G*D = 2^21
    int d = i & 63;
    int g = (i >> 6) & 7;
    int s = (i >> 9) & 2047;
    int b = i >> 20;
    out[(((size_t)b * G_ + g) * S_ + s) * D_ + d] = in[i];
}

// ---------------------------------------------------------------------------
// Flash attention, causal, GQA. Q:[B,H,S,D], K/V:[B,G,S,D], ctx:[B,S,H*D].
// Block = 128 threads, 64-query tile, 64-key tiles.
// Thread mapping: r = tid&63 (query row), half = tid>>6 (key/col half).
// ---------------------------------------------------------------------------
#define PADW 65
#define SMEM_ATTN ((4 * 64 * PADW + 256) * 4)

__global__ __launch_bounds__(128) void attn_kernel(
    const float* __restrict__ Q, const float* __restrict__ K,
    const float* __restrict__ V, float* __restrict__ ctx)
{
    extern __shared__ float sm[];
    float* Qs = sm;                      // 64 x 65
    float* Ks = Qs + 64 * PADW;
    float* Vs = Ks + 64 * PADW;
    float* Ss = Vs + 64 * PADW;
    float* redm = Ss + 64 * PADW;        // 2 x 64
    float* reds = redm + 128;            // 2 x 64

    int qt = blockIdx.x;
    int h = blockIdx.y;
    int b = blockIdx.z;
    int g = h / GS_;
    int tid = threadIdx.x;
    int r = tid & 63;
    int half = tid >> 6;

    const float* Qp = Q + (((size_t)b * H_ + h) * S_ + qt * 64) * D_;
    for (int i = tid; i < 64 * D_; i += 128)
        Qs[(i >> 6) * PADW + (i & 63)] = Qp[i];

    float m_run = -1e30f, l_run = 0.f;
    float o[32];
#pragma unroll
    for (int c = 0; c < 32; c++) o[c] = 0.f;

    const float* Kbase = K + ((size_t)b * G_ + g) * S_ * D_;
    const float* Vbase = V + ((size_t)b * G_ + g) * S_ * D_;
    int qglob = qt * 64 + r;

    for (int kt = 0; kt <= qt; kt++) {
        __syncthreads();
        const float* Kp = Kbase + (size_t)kt * 64 * D_;
        const float* Vp = Vbase + (size_t)kt * 64 * D_;
        for (int i = tid; i < 64 * D_; i += 128) {
            Ks[(i >> 6) * PADW + (i & 63)] = Kp[i];
            Vs[(i >> 6) * PADW + (i & 63)] = Vp[i];
        }
        __syncthreads();

        // scores: 32 keys per thread (keys half*32 .. half*32+31)
        float acc[32];
#pragma unroll
        for (int j = 0; j < 32; j++) acc[j] = 0.f;
        for (int d = 0; d < 64; d++) {
            float qv = Qs[r * PADW + d];
#pragma unroll
            for (int j = 0; j < 32; j++)
                acc[j] += qv * Ks[(half * 32 + j) * PADW + d];
        }
        float lmax = -1e30f;
#pragma unroll
        for (int j = 0; j < 32; j++) {
            int kg = kt * 64 + half * 32 + j;
            acc[j] = (kg <= qglob) ? acc[j] * 0.125f : -1e30f;
            lmax = fmaxf(lmax, acc[j]);
        }
        redm[half * 64 + r] = lmax;
        __syncthreads();
        float mt = fmaxf(redm[r], redm[64 + r]);
        float m_new = fmaxf(m_run, mt);
        float lsum = 0.f;
#pragma unroll
        for (int j = 0; j < 32; j++) {
            float p = __expf(acc[j] - m_new);
            Ss[r * PADW + half * 32 + j] = p;
            lsum += p;
        }
        reds[half * 64 + r] = lsum;
        __syncthreads();
        float alpha = __expf(m_run - m_new);
        l_run = l_run * alpha + reds[r] + reds[64 + r];
        m_run = m_new;
#pragma unroll
        for (int c = 0; c < 32; c++) o[c] *= alpha;
        for (int j = 0; j < 64; j++) {
            float p = Ss[r * PADW + j];
#pragma unroll
            for (int c = 0; c < 32; c++)
                o[c] += p * Vs[j * PADW + half * 32 + c];
        }
    }

    float inv = 1.f / l_run;
    __syncthreads();
#pragma unroll
    for (int c = 0; c < 32; c++) Ss[r * PADW + half * 32 + c] = o[c] * inv;
    __syncthreads();

    float* Cp = ctx + ((size_t)b * S_ + qt * 64) * HD_ + h * D_;
    for (int i = tid; i < 64 * 64; i += 128)
        Cp[(i >> 6) * HD_ + (i & 63)] = Ss[(i >> 6) * PADW + (i & 63)];
}

// ---------------------------------------------------------------------------
extern "C" void kernel_launch(void* const* d_in, const int* in_sizes, int n_in,
                              void* d_out, int out_size)
{
    const float* x    = (const float*)d_in[0];
    // d_in[1] = mask (causal triu; implemented analytically, unused)
    const float* cosp = (const float*)d_in[2];
    const float* sinp = (const float*)d_in[3];
    const float* Wq   = (const float*)d_in[4];
    const float* Wk   = (const float*)d_in[5];
    const float* Wv   = (const float*)d_in[6];
    const float* Wo   = (const float*)d_in[7];
    const float* qsc  = (const float*)d_in[8];
    const float* ksc  = (const float*)d_in[9];

    float* out = (float*)d_out;
    float* k_out = out + (size_t)B_ * S_ * DIN_;          // [B,G,S,D]
    float* v_out = k_out + (size_t)B_ * G_ * S_ * D_;     // [B,G,S,D]

    float *q_raw, *k_raw, *v_raw, *q_att, *ctx;
    cudaGetSymbolAddress((void**)&q_raw, g_q_raw);
    cudaGetSymbolAddress((void**)&k_raw, g_k_raw);
    cudaGetSymbolAddress((void**)&v_raw, g_v_raw);
    cudaGetSymbolAddress((void**)&q_att, g_q_att);
    cudaGetSymbolAddress((void**)&ctx,   g_ctx);

    const int M = B_ * S_;  // 4096

    // QKV projections
    sgemm_kernel<<<dim3(HD_ / BN, M / BM), 256>>>(x, Wq, q_raw, M, HD_, DIN_);
    sgemm_kernel<<<dim3(GD_ / BN, M / BM), 256>>>(x, Wk, k_raw, M, GD_, DIN_);
    sgemm_kernel<<<dim3(GD_ / BN, M / BM), 256>>>(x, Wv, v_raw, M, GD_, DIN_);

    // RMSNorm + RoPE (q -> scratch [B,H,S,D]; k -> output slot [B,G,S,D])
    normrope_kernel<<<(B_ * S_ * H_) / 4, 128>>>(q_raw, q_att, qsc, cosp, sinp, H_);
    normrope_kernel<<<(B_ * S_ * G_) / 4, 128>>>(k_raw, k_out, ksc, cosp, sinp, G_);

    // v -> output slot [B,G,S,D]
    vtrans_kernel<<<(B_ * S_ * GD_) / 256, 256>>>(v_raw, v_out);

    // Attention
    cudaFuncSetAttribute(attn_kernel, cudaFuncAttributeMaxDynamicSharedMemorySize,
                         SMEM_ATTN);
    attn_kernel<<<dim3(S_ / 64, H_, B_), 128, SMEM_ATTN>>>(q_att, k_out, v_out, ctx);

    // Output projection
    sgemm_kernel<<<dim3(DIN_ / BN, M / BM), 256>>>(ctx, Wo, out, M, DIN_, DIN_);
}

// round 5
// speedup vs baseline: 2.1786x; 2.1786x over previous
#include <cuda_runtime.h>
#include <cuda_bf16.h>
#include <cstdint>

#define B_ 2
#define S_ 2048
#define DIN_ 2048
#define H_ 32
#define G_ 8
#define D_ 64
#define GS_ (H_ / G_)
#define HD_ (H_ * D_)
#define GD_ (G_ * D_)

// Scratch (static device globals; allocation APIs are forbidden)
__device__ float g_q_raw[B_ * S_ * HD_];   // [B*S, H*D]
__device__ float g_k_raw[B_ * S_ * GD_];   // [B*S, G*D]
__device__ float g_v_raw[B_ * S_ * GD_];   // [B*S, G*D]
__device__ float g_q_att[B_ * S_ * HD_];   // [B, H, S, D]
__device__ float g_ctx[B_ * S_ * HD_];     // [B, S, H*D]

// ---------------------------------------------------------------------------
// TF32 tensor-core GEMM: C[M,N] = A[M,K] @ B[K,N], row-major fp32 in/out.
// CTA tile 128x128, K-step 16, 256 threads = 8 warps (2m x 4n).
// Warp tile 64x32 -> 4x4 fragments of mma.sync.m16n8k8.tf32.
// ---------------------------------------------------------------------------
#define TM 128
#define TN 128
#define TK 16
#define PADA 20    // As[m][k] row pad
#define PADB 136   // Bs[k][n] row pad

__device__ __forceinline__ uint32_t f2tf32(float f) {
    uint32_t r;
    asm("cvt.rna.tf32.f32 %0, %1;" : "=r"(r) : "f"(f));
    return r;
}

__device__ __forceinline__ void mma_tf32(
    float& c0, float& c1, float& c2, float& c3,
    uint32_t a0, uint32_t a1, uint32_t a2, uint32_t a3,
    uint32_t b0, uint32_t b1)
{
    asm volatile(
        "mma.sync.aligned.m16n8k8.row.col.f32.tf32.tf32.f32 "
        "{%0,%1,%2,%3}, {%4,%5,%6,%7}, {%8,%9}, {%0,%1,%2,%3};"
        : "+f"(c0), "+f"(c1), "+f"(c2), "+f"(c3)
        : "r"(a0), "r"(a1), "r"(a2), "r"(a3), "r"(b0), "r"(b1));
}

__global__ __launch_bounds__(256) void tf32_gemm_kernel(
    const float* __restrict__ A, const float* __restrict__ Bm,
    float* __restrict__ C, int M, int N, int K)
{
    __shared__ uint32_t As[TM][PADA];   // [m][k], tf32 bit patterns
    __shared__ uint32_t Bs[TK][PADB];   // [k][n]

    int tid = threadIdx.x;
    int lane = tid & 31;
    int wid = tid >> 5;
    int gid = lane >> 2;    // 0..7
    int tig = lane & 3;     // 0..3
    int warp_m = wid >> 2;  // 0..1
    int warp_n = wid & 3;   // 0..3
    int wm = warp_m * 64;
    int wn = warp_n * 32;
    int m0 = blockIdx.y * TM;
    int n0 = blockIdx.x * TN;

    int aRow = tid >> 1;          // 0..127
    int aCol = (tid & 1) * 8;     // 0 or 8
    int bRow = tid >> 4;          // 0..15
    int bCol = (tid & 15) * 8;    // 0..120

    const float* Ap = A + (size_t)(m0 + aRow) * K + aCol;
    const float* Bp = Bm + (size_t)bRow * N + n0 + bCol;

    float acc[4][4][4];
#pragma unroll
    for (int i = 0; i < 4; i++)
#pragma unroll
        for (int j = 0; j < 4; j++)
#pragma unroll
            for (int r = 0; r < 4; r++) acc[i][j][r] = 0.f;

    float4 pa0 = *(const float4*)(Ap + 0);
    float4 pa1 = *(const float4*)(Ap + 4);
    float4 pb0 = *(const float4*)(Bp + 0);
    float4 pb1 = *(const float4*)(Bp + 4);

    for (int k0 = 0; k0 < K; k0 += TK) {
        {
            uint4 va0 = make_uint4(f2tf32(pa0.x), f2tf32(pa0.y), f2tf32(pa0.z), f2tf32(pa0.w));
            uint4 va1 = make_uint4(f2tf32(pa1.x), f2tf32(pa1.y), f2tf32(pa1.z), f2tf32(pa1.w));
            *(uint4*)&As[aRow][aCol + 0] = va0;
            *(uint4*)&As[aRow][aCol + 4] = va1;
            uint4 vb0 = make_uint4(f2tf32(pb0.x), f2tf32(pb0.y), f2tf32(pb0.z), f2tf32(pb0.w));
            uint4 vb1 = make_uint4(f2tf32(pb1.x), f2tf32(pb1.y), f2tf32(pb1.z), f2tf32(pb1.w));
            *(uint4*)&Bs[bRow][bCol + 0] = vb0;
            *(uint4*)&Bs[bRow][bCol + 4] = vb1;
        }
        __syncthreads();

        if (k0 + TK < K) {
            pa0 = *(const float4*)(Ap + k0 + TK);
            pa1 = *(const float4*)(Ap + k0 + TK + 4);
            pb0 = *(const float4*)(Bp + (size_t)(k0 + TK) * N);
            pb1 = *(const float4*)(Bp + (size_t)(k0 + TK) * N + 4);
        }

#pragma unroll
        for (int ks = 0; ks < TK; ks += 8) {
            uint32_t af[4][4];
#pragma unroll
            for (int mf = 0; mf < 4; mf++) {
                int mr = wm + mf * 16 + gid;
                af[mf][0] = As[mr][ks + tig];
                af[mf][1] = As[mr + 8][ks + tig];
                af[mf][2] = As[mr][ks + tig + 4];
                af[mf][3] = As[mr + 8][ks + tig + 4];
            }
            uint32_t bf[4][2];
#pragma unroll
            for (int nf = 0; nf < 4; nf++) {
                int nc = wn + nf * 8 + gid;
                bf[nf][0] = Bs[ks + tig][nc];
                bf[nf][1] = Bs[ks + tig + 4][nc];
            }
#pragma unroll
            for (int mf = 0; mf < 4; mf++)
#pragma unroll
                for (int nf = 0; nf < 4; nf++)
                    mma_tf32(acc[mf][nf][0], acc[mf][nf][1], acc[mf][nf][2], acc[mf][nf][3],
                             af[mf][0], af[mf][1], af[mf][2], af[mf][3],
                             bf[nf][0], bf[nf][1]);
        }
        __syncthreads();
    }

#pragma unroll
    for (int mf = 0; mf < 4; mf++) {
#pragma unroll
        for (int nf = 0; nf < 4; nf++) {
            int row = m0 + wm + mf * 16 + gid;
            int col = n0 + wn + nf * 8 + 2 * tig;
            *(float2*)&C[(size_t)row * N + col] =
                make_float2(acc[mf][nf][0], acc[mf][nf][1]);
            *(float2*)&C[(size_t)(row + 8) * N + col] =
                make_float2(acc[mf][nf][2], acc[mf][nf][3]);
        }
    }
}

// ---------------------------------------------------------------------------
// RMSNorm + RoPE. One warp per (b,s,head). in: [B*S, NH*D]; out: [B, NH, S, D]
// ---------------------------------------------------------------------------
__global__ void normrope_kernel(const float* __restrict__ in,
                                float* __restrict__ out,
                                const float* __restrict__ scale,
                                const float* __restrict__ cosp,
                                const float* __restrict__ sinp,
                                int NH)
{
    int w = (blockIdx.x * blockDim.x + threadIdx.x) >> 5;
    int lane = threadIdx.x & 31;
    int nh = w % NH;
    int bs = w / NH;          // b*S + s
    int s = bs % S_;
    int b = bs / S_;

    const float* row = in + (size_t)bs * NH * D_ + nh * D_;
    float x0 = row[lane];
    float x1 = row[lane + 32];
    float ss = x0 * x0 + x1 * x1;
#pragma unroll
    for (int o = 16; o > 0; o >>= 1) ss += __shfl_xor_sync(0xffffffffu, ss, o);
    float rinv = rsqrtf(ss * (1.0f / 64.0f) + 1e-6f);
    float n0 = x0 * rinv * scale[lane];
    float n1 = x1 * rinv * scale[lane + 32];

    float c0 = cosp[s * D_ + lane];
    float c1 = cosp[s * D_ + lane + 32];
    float s0 = sinp[s * D_ + lane];
    float s1 = sinp[s * D_ + lane + 32];
    float r0 = n0 * c0 - n1 * s0;
    float r1 = n1 * c1 + n0 * s1;

    float* orow = out + (((size_t)b * NH + nh) * S_ + s) * D_;
    orow[lane] = r0;
    orow[lane + 32] = r1;
}

// ---------------------------------------------------------------------------
// V transpose: [b,s,g,d] -> [b,g,s,d]
// ---------------------------------------------------------------------------
__global__ void vtrans_kernel(const float* __restrict__ in, float* __restrict__ out)
{
    int i = blockIdx.x * blockDim.x + threadIdx.x;
    int d = i & 63;
    int g = (i >> 6) & 7;
    int s = (i >> 9) & 2047;
    int b = i >> 20;
    out[(((size_t)b * G_ + g) * S_ + s) * D_ + d] = in[i];
}

// ---------------------------------------------------------------------------
// Flash attention, causal, GQA. Q:[B,H,S,D], K/V:[B,G,S,D], ctx:[B,S,H*D].
// 128 threads, 64x64 tiles. Register blocking 4 queries x 8 keys per thread:
//   queries: (tid&15) + 16*i   (i=0..3)
//   keys/dcols: (tid>>4) + 8*j (j=0..7)
// LDS:FFMA ratio 12:32 -> FFMA-bound (fp32 floor).
// ---------------------------------------------------------------------------
#define PADW 65
#define SMEM_ATTN ((4 * 64 * PADW + 1024) * 4)

__global__ __launch_bounds__(128) void attn_kernel(
    const float* __restrict__ Q, const float* __restrict__ K,
    const float* __restrict__ V, float* __restrict__ ctx)
{
    extern __shared__ float sm[];
    float* Qs = sm;                      // 64 x 65
    float* Ks = Qs + 64 * PADW;
    float* Vs = Ks + 64 * PADW;
    float* Ss = Vs + 64 * PADW;
    float* redm = Ss + 64 * PADW;        // 64 x 8 partial maxes
    float* reds = redm + 512;            // 64 x 8 partial sums

    int qt = blockIdx.x;
    int h = blockIdx.y;
    int b = blockIdx.z;
    int g = h / GS_;
    int tid = threadIdx.x;
    int qi = tid & 15;    // query base: qi + 16*i
    int kj = tid >> 4;    // key/dcol base: kj + 8*j

    const float* Qp = Q + (((size_t)b * H_ + h) * S_ + qt * 64) * D_;
    for (int i = tid; i < 64 * D_; i += 128)
        Qs[(i >> 6) * PADW + (i & 63)] = Qp[i];

    float m_run[4], l_run[4], o[4][8];
#pragma unroll
    for (int i = 0; i < 4; i++) {
        m_run[i] = -1e30f;
        l_run[i] = 0.f;
#pragma unroll
        for (int j = 0; j < 8; j++) o[i][j] = 0.f;
    }

    const float* Kbase = K + ((size_t)b * G_ + g) * S_ * D_;
    const float* Vbase = V + ((size_t)b * G_ + g) * S_ * D_;

    for (int kt = 0; kt <= qt; kt++) {
        __syncthreads();
        const float* Kp = Kbase + (size_t)kt * 64 * D_;
        const float* Vp = Vbase + (size_t)kt * 64 * D_;
        for (int i = tid; i < 64 * D_; i += 128) {
            Ks[(i >> 6) * PADW + (i & 63)] = Kp[i];
            Vs[(i >> 6) * PADW + (i & 63)] = Vp[i];
        }
        __syncthreads();

        // --- scores: acc[i][j] = Q[qi+16i] . K[kj+8j] ---
        float acc[4][8];
#pragma unroll
        for (int i = 0; i < 4; i++)
#pragma unroll
            for (int j = 0; j < 8; j++) acc[i][j] = 0.f;

#pragma unroll 4
        for (int d = 0; d < 64; d++) {
            float qv[4], kv[8];
#pragma unroll
            for (int i = 0; i < 4; i++) qv[i] = Qs[(qi + 16 * i) * PADW + d];
#pragma unroll
            for (int j = 0; j < 8; j++) kv[j] = Ks[(kj + 8 * j) * PADW + d];
#pragma unroll
            for (int i = 0; i < 4; i++)
#pragma unroll
                for (int j = 0; j < 8; j++) acc[i][j] += qv[i] * kv[j];
        }

        // --- mask + scale + per-thread partial max ---
        bool full = (kt < qt);  // full tiles need no masking
#pragma unroll
        for (int i = 0; i < 4; i++) {
            int qglob = qt * 64 + qi + 16 * i;
            float pm = -1e30f;
#pragma unroll
            for (int j = 0; j < 8; j++) {
                int kglob = kt * 64 + kj + 8 * j;
                acc[i][j] = (full || kglob <= qglob) ? acc[i][j] * 0.125f : -1e30f;
                pm = fmaxf(pm, acc[i][j]);
            }
            redm[(qi + 16 * i) * 8 + kj] = pm;
        }
        __syncthreads();

        // --- per-query tile max, p = exp, partial sums, write P ---
        float alpha[4];
#pragma unroll
        for (int i = 0; i < 4; i++) {
            int q = qi + 16 * i;
            float mt = redm[q * 8 + 0];
#pragma unroll
            for (int w = 1; w < 8; w++) mt = fmaxf(mt, redm[q * 8 + w]);
            float m_new = fmaxf(m_run[i], mt);
            alpha[i] = __expf(m_run[i] - m_new);
            m_run[i] = m_new;
            float ps = 0.f;
#pragma unroll
            for (int j = 0; j < 8; j++) {
                float p = __expf(acc[i][j] - m_new);
                Ss[q * PADW + kj + 8 * j] = p;
                ps += p;
            }
            reds[q * 8 + kj] = ps;
        }
        __syncthreads();

#pragma unroll
        for (int i = 0; i < 4; i++) {
            int q = qi + 16 * i;
            float ts = 0.f;
#pragma unroll
            for (int w = 0; w < 8; w++) ts += reds[q * 8 + w];
            l_run[i] = l_run[i] * alpha[i] + ts;
#pragma unroll
            for (int j = 0; j < 8; j++) o[i][j] *= alpha[i];
        }

        // --- PV: o[i][j] += P[q][k] * V[k][dcol] ---
#pragma unroll 4
        for (int k = 0; k < 64; k++) {
            float pv[4], vv[8];
#pragma unroll
            for (int i = 0; i < 4; i++) pv[i] = Ss[(qi + 16 * i) * PADW + k];
#pragma unroll
            for (int j = 0; j < 8; j++) vv[j] = Vs[k * PADW + kj + 8 * j];
#pragma unroll
            for (int i = 0; i < 4; i++)
#pragma unroll
                for (int j = 0; j < 8; j++) o[i][j] += pv[i] * vv[j];
        }
    }

    // --- normalize, stage in smem, coalesced store ---
    __syncthreads();
#pragma unroll
    for (int i = 0; i < 4; i++) {
        float inv = 1.f / l_run[i];
#pragma unroll
        for (int j = 0; j < 8; j++)
            Ss[(qi + 16 * i) * PADW + kj + 8 * j] = o[i][j] * inv;
    }
    __syncthreads();

    float* Cp = ctx + ((size_t)b * S_ + qt * 64) * HD_ + h * D_;
    for (int i = tid; i < 64 * 64; i += 128)
        Cp[(i >> 6) * HD_ + (i & 63)] = Ss[(i >> 6) * PADW + (i & 63)];
}

// ---------------------------------------------------------------------------
extern "C" void kernel_launch(void* const* d_in, const int* in_sizes, int n_in,
                              void* d_out, int out_size)
{
    const float* x    = (const float*)d_in[0];
    // d_in[1] = mask (causal; handled analytically)
    const float* cosp = (const float*)d_in[2];
    const float* sinp = (const float*)d_in[3];
    const float* Wq   = (const float*)d_in[4];
    const float* Wk   = (const float*)d_in[5];
    const float* Wv   = (const float*)d_in[6];
    const float* Wo   = (const float*)d_in[7];
    const float* qsc  = (const float*)d_in[8];
    const float* ksc  = (const float*)d_in[9];

    float* out = (float*)d_out;
    float* k_out = out + (size_t)B_ * S_ * DIN_;          // [B,G,S,D]
    float* v_out = k_out + (size_t)B_ * G_ * S_ * D_;     // [B,G,S,D]

    float *q_raw, *k_raw, *v_raw, *q_att, *ctx;
    cudaGetSymbolAddress((void**)&q_raw, g_q_raw);
    cudaGetSymbolAddress((void**)&k_raw, g_k_raw);
    cudaGetSymbolAddress((void**)&v_raw, g_v_raw);
    cudaGetSymbolAddress((void**)&q_att, g_q_att);
    cudaGetSymbolAddress((void**)&ctx,   g_ctx);

    const int M = B_ * S_;  // 4096

    // QKV projections (tf32 tensor cores)
    tf32_gemm_kernel<<<dim3(HD_ / TN, M / TM), 256>>>(x, Wq, q_raw, M, HD_, DIN_);
    tf32_gemm_kernel<<<dim3(GD_ / TN, M / TM), 256>>>(x, Wk, k_raw, M, GD_, DIN_);
    tf32_gemm_kernel<<<dim3(GD_ / TN, M / TM), 256>>>(x, Wv, v_raw, M, GD_, DIN_);

    // RMSNorm + RoPE (q -> scratch [B,H,S,D]; k -> output slot [B,G,S,D])
    normrope_kernel<<<(B_ * S_ * H_) / 4, 128>>>(q_raw, q_att, qsc, cosp, sinp, H_);
    normrope_kernel<<<(B_ * S_ * G_) / 4, 128>>>(k_raw, k_out, ksc, cosp, sinp, G_);

    // v -> output slot [B,G,S,D]
    vtrans_kernel<<<(B_ * S_ * GD_) / 256, 256>>>(v_raw, v_out);

    // Attention
    cudaFuncSetAttribute(attn_kernel, cudaFuncAttributeMaxDynamicSharedMemorySize,
                         SMEM_ATTN);
    attn_kernel<<<dim3(S_ / 64, H_, B_), 128, SMEM_ATTN>>>(q_att, k_out, v_out, ctx);

    // Output projection (tf32 tensor cores)
    tf32_gemm_kernel<<<dim3(DIN_ / TN, M / TM), 256>>>(ctx, Wo, out, M, DIN_, DIN_);
}

// round 6
// speedup vs baseline: 3.2633x; 1.4979x over previous
#include <cuda_runtime.h>
#include <cuda_bf16.h>
#include <cstdint>

#define B_ 2
#define S_ 2048
#define DIN_ 2048
#define H_ 32
#define G_ 8
#define D_ 64
#define GS_ (H_ / G_)
#define HD_ (H_ * D_)
#define GD_ (G_ * D_)

// Scratch (static device globals; allocation APIs are forbidden)
__device__ float g_q_raw[B_ * S_ * HD_];   // [B*S, H*D]
__device__ float g_k_raw[B_ * S_ * GD_];   // [B*S, G*D]
__device__ float g_v_raw[B_ * S_ * GD_];   // [B*S, G*D]
__device__ float g_q_att[B_ * S_ * HD_];   // [B, H, S, D]
__device__ float g_ctx[B_ * S_ * HD_];     // [B, S, H*D]

// ---------------------------------------------------------------------------
// Shared tf32 helpers
// ---------------------------------------------------------------------------
__device__ __forceinline__ uint32_t f2tf32(float f) {
    uint32_t r;
    asm("cvt.rna.tf32.f32 %0, %1;" : "=r"(r) : "f"(f));
    return r;
}

__device__ __forceinline__ void mma_tf32(
    float& c0, float& c1, float& c2, float& c3,
    uint32_t a0, uint32_t a1, uint32_t a2, uint32_t a3,
    uint32_t b0, uint32_t b1)
{
    asm volatile(
        "mma.sync.aligned.m16n8k8.row.col.f32.tf32.tf32.f32 "
        "{%0,%1,%2,%3}, {%4,%5,%6,%7}, {%8,%9}, {%0,%1,%2,%3};"
        : "+f"(c0), "+f"(c1), "+f"(c2), "+f"(c3)
        : "r"(a0), "r"(a1), "r"(a2), "r"(a3), "r"(b0), "r"(b1));
}

// Fast exp2 on FMA/ALU pipes (avoids the MUFU floor).
// exp2p(z) = 2^z, z <= ~0; clamped below -125. Rel err ~2.4e-6.
__device__ __forceinline__ float exp2p(float z) {
    z = fmaxf(z, -125.0f);
    float n = rintf(z);
    float t = (z - n) * 0.6931471805599453f;   // |t| <= 0.3466
    float p = 1.0f + t * (1.0f + t * (0.5f + t * (0.16666667f +
              t * (0.041666668f + t * 0.008333334f))));
    int ni = (int)n;
    return p * __int_as_float((ni + 127) << 23);
}

// ---------------------------------------------------------------------------
// TF32 tensor-core GEMM: C[M,N] = A[M,K] @ B[K,N]  (unchanged from R5)
// ---------------------------------------------------------------------------
#define TM 128
#define TN 128
#define TK 16
#define PADA 20
#define PADB 136

__global__ __launch_bounds__(256) void tf32_gemm_kernel(
    const float* __restrict__ A, const float* __restrict__ Bm,
    float* __restrict__ C, int M, int N, int K)
{
    __shared__ uint32_t As[TM][PADA];
    __shared__ uint32_t Bs[TK][PADB];

    int tid = threadIdx.x;
    int lane = tid & 31;
    int wid = tid >> 5;
    int gid = lane >> 2;
    int tig = lane & 3;
    int warp_m = wid >> 2;
    int warp_n = wid & 3;
    int wm = warp_m * 64;
    int wn = warp_n * 32;
    int m0 = blockIdx.y * TM;
    int n0 = blockIdx.x * TN;

    int aRow = tid >> 1;
    int aCol = (tid & 1) * 8;
    int bRow = tid >> 4;
    int bCol = (tid & 15) * 8;

    const float* Ap = A + (size_t)(m0 + aRow) * K + aCol;
    const float* Bp = Bm + (size_t)bRow * N + n0 + bCol;

    float acc[4][4][4];
#pragma unroll
    for (int i = 0; i < 4; i++)
#pragma unroll
        for (int j = 0; j < 4; j++)
#pragma unroll
            for (int r = 0; r < 4; r++) acc[i][j][r] = 0.f;

    float4 pa0 = *(const float4*)(Ap + 0);
    float4 pa1 = *(const float4*)(Ap + 4);
    float4 pb0 = *(const float4*)(Bp + 0);
    float4 pb1 = *(const float4*)(Bp + 4);

    for (int k0 = 0; k0 < K; k0 += TK) {
        {
            uint4 va0 = make_uint4(f2tf32(pa0.x), f2tf32(pa0.y), f2tf32(pa0.z), f2tf32(pa0.w));
            uint4 va1 = make_uint4(f2tf32(pa1.x), f2tf32(pa1.y), f2tf32(pa1.z), f2tf32(pa1.w));
            *(uint4*)&As[aRow][aCol + 0] = va0;
            *(uint4*)&As[aRow][aCol + 4] = va1;
            uint4 vb0 = make_uint4(f2tf32(pb0.x), f2tf32(pb0.y), f2tf32(pb0.z), f2tf32(pb0.w));
            uint4 vb1 = make_uint4(f2tf32(pb1.x), f2tf32(pb1.y), f2tf32(pb1.z), f2tf32(pb1.w));
            *(uint4*)&Bs[bRow][bCol + 0] = vb0;
            *(uint4*)&Bs[bRow][bCol + 4] = vb1;
        }
        __syncthreads();

        if (k0 + TK < K) {
            pa0 = *(const float4*)(Ap + k0 + TK);
            pa1 = *(const float4*)(Ap + k0 + TK + 4);
            pb0 = *(const float4*)(Bp + (size_t)(k0 + TK) * N);
            pb1 = *(const float4*)(Bp + (size_t)(k0 + TK) * N + 4);
        }

#pragma unroll
        for (int ks = 0; ks < TK; ks += 8) {
            uint32_t af[4][4];
#pragma unroll
            for (int mf = 0; mf < 4; mf++) {
                int mr = wm + mf * 16 + gid;
                af[mf][0] = As[mr][ks + tig];
                af[mf][1] = As[mr + 8][ks + tig];
                af[mf][2] = As[mr][ks + tig + 4];
                af[mf][3] = As[mr + 8][ks + tig + 4];
            }
            uint32_t bf[4][2];
#pragma unroll
            for (int nf = 0; nf < 4; nf++) {
                int nc = wn + nf * 8 + gid;
                bf[nf][0] = Bs[ks + tig][nc];
                bf[nf][1] = Bs[ks + tig + 4][nc];
            }
#pragma unroll
            for (int mf = 0; mf < 4; mf++)
#pragma unroll
                for (int nf = 0; nf < 4; nf++)
                    mma_tf32(acc[mf][nf][0], acc[mf][nf][1], acc[mf][nf][2], acc[mf][nf][3],
                             af[mf][0], af[mf][1], af[mf][2], af[mf][3],
                             bf[nf][0], bf[nf][1]);
        }
        __syncthreads();
    }

#pragma unroll
    for (int mf = 0; mf < 4; mf++) {
#pragma unroll
        for (int nf = 0; nf < 4; nf++) {
            int row = m0 + wm + mf * 16 + gid;
            int col = n0 + wn + nf * 8 + 2 * tig;
            *(float2*)&C[(size_t)row * N + col] =
                make_float2(acc[mf][nf][0], acc[mf][nf][1]);
            *(float2*)&C[(size_t)(row + 8) * N + col] =
                make_float2(acc[mf][nf][2], acc[mf][nf][3]);
        }
    }
}

// ---------------------------------------------------------------------------
// RMSNorm + RoPE (unchanged)
// ---------------------------------------------------------------------------
__global__ void normrope_kernel(const float* __restrict__ in,
                                float* __restrict__ out,
                                const float* __restrict__ scale,
                                const float* __restrict__ cosp,
                                const float* __restrict__ sinp,
                                int NH)
{
    int w = (blockIdx.x * blockDim.x + threadIdx.x) >> 5;
    int lane = threadIdx.x & 31;
    int nh = w % NH;
    int bs = w / NH;
    int s = bs % S_;
    int b = bs / S_;

    const float* row = in + (size_t)bs * NH * D_ + nh * D_;
    float x0 = row[lane];
    float x1 = row[lane + 32];
    float ss = x0 * x0 + x1 * x1;
#pragma unroll
    for (int o = 16; o > 0; o >>= 1) ss += __shfl_xor_sync(0xffffffffu, ss, o);
    float rinv = rsqrtf(ss * (1.0f / 64.0f) + 1e-6f);
    float n0 = x0 * rinv * scale[lane];
    float n1 = x1 * rinv * scale[lane + 32];

    float c0 = cosp[s * D_ + lane];
    float c1 = cosp[s * D_ + lane + 32];
    float s0 = sinp[s * D_ + lane];
    float s1 = sinp[s * D_ + lane + 32];
    float r0 = n0 * c0 - n1 * s0;
    float r1 = n1 * c1 + n0 * s1;

    float* orow = out + (((size_t)b * NH + nh) * S_ + s) * D_;
    orow[lane] = r0;
    orow[lane + 32] = r1;
}

// ---------------------------------------------------------------------------
// V transpose: [b,s,g,d] -> [b,g,s,d] (unchanged)
// ---------------------------------------------------------------------------
__global__ void vtrans_kernel(const float* __restrict__ in, float* __restrict__ out)
{
    int i = blockIdx.x * blockDim.x + threadIdx.x;
    int d = i & 63;
    int g = (i >> 6) & 7;
    int s = (i >> 9) & 2047;
    int b = i >> 20;
    out[(((size_t)b * G_ + g) * S_ + s) * D_ + d] = in[i];
}

// ---------------------------------------------------------------------------
// Tensor-core flash attention, causal, GQA.
// 128 threads = 4 warps; CTA tile 64q x 64k; warp owns 16 q rows.
// QK^T: tf32 mma (A=Q, B=K).  PV computed transposed: O^T = V^T * P^T
//   (A = V^T read from natural Vs[k][d], B = P^T read from Ps[q][k]).
// Softmax in log2 domain with FMA-pipe exp2 polynomial (MUFU idle).
// ---------------------------------------------------------------------------
#define APAD 68   // Qs/Ks/Ps pad: fragment banks = 4*gid+tig = lane (conflict-free)
#define VPAD 72   // Vs pad: A-fragment banks = 8*tig+gid (conflict-free)
#define SMEM_ATC ((64 * APAD * 3 + 64 * VPAD + 128) * 4)

__global__ __launch_bounds__(128) void attn_tc_kernel(
    const float* __restrict__ Q, const float* __restrict__ K,
    const float* __restrict__ V, float* __restrict__ ctx)
{
    extern __shared__ uint32_t smu[];
    uint32_t* Qs = smu;                     // [64][APAD] tf32
    uint32_t* Ks = Qs + 64 * APAD;          // [64][APAD] tf32
    uint32_t* Ps = Ks + 64 * APAD;          // [64][APAD] tf32
    uint32_t* Vs = Ps + 64 * APAD;          // [64][VPAD] tf32
    float* alpha_sm = (float*)(Vs + 64 * VPAD);  // [64]
    float* linv_sm  = alpha_sm + 64;             // [64]

    int qt = (int)gridDim.x - 1 - (int)blockIdx.x;  // longest first
    int h = blockIdx.y;
    int b = blockIdx.z;
    int g = h / GS_;
    int tid = threadIdx.x;
    int lane = tid & 31;
    int wid = tid >> 5;     // 0..3, owns q rows [wid*16, wid*16+16)
    int gid = lane >> 2;    // 0..7
    int tig = lane & 3;     // 0..3

    const float SC = 0.125f * 1.4426950408889634f;  // scale * log2(e)

    // Load Q tile (tf32)
    const float* Qp = Q + (((size_t)b * H_ + h) * S_ + qt * 64) * D_;
    for (int i = tid; i < 64 * D_; i += 128)
        Qs[(i >> 6) * APAD + (i & 63)] = f2tf32(Qp[i]);

    // O^T accumulators: [mt(d)][ntq(q)][4]
    float o[4][2][4];
#pragma unroll
    for (int mt = 0; mt < 4; mt++)
#pragma unroll
        for (int nq = 0; nq < 2; nq++)
#pragma unroll
            for (int r = 0; r < 4; r++) o[mt][nq][r] = 0.f;
    float m_run0 = -1e30f, m_run1 = -1e30f;
    float l_run0 = 0.f, l_run1 = 0.f;

    const float* Kbase = K + ((size_t)b * G_ + g) * S_ * D_;
    const float* Vbase = V + ((size_t)b * G_ + g) * S_ * D_;

    for (int kt = 0; kt <= qt; kt++) {
        __syncthreads();
        const float* Kp = Kbase + (size_t)kt * 64 * D_;
        const float* Vp = Vbase + (size_t)kt * 64 * D_;
        for (int i = tid; i < 64 * D_; i += 128) {
            int r = i >> 6, c = i & 63;
            Ks[r * APAD + c] = f2tf32(Kp[i]);
            Vs[r * VPAD + c] = f2tf32(Vp[i]);
        }
        __syncthreads();

        // ---- QK^T: s[nt][4] covers q rows {w16+gid, +8} x k cols {8nt+2tig, +1}
        float s[8][4];
#pragma unroll
        for (int nt = 0; nt < 8; nt++)
#pragma unroll
            for (int r = 0; r < 4; r++) s[nt][r] = 0.f;

        int qrow = wid * 16 + gid;
#pragma unroll
        for (int kk = 0; kk < 64; kk += 8) {
            uint32_t a0 = Qs[qrow * APAD + kk + tig];
            uint32_t a1 = Qs[(qrow + 8) * APAD + kk + tig];
            uint32_t a2 = Qs[qrow * APAD + kk + tig + 4];
            uint32_t a3 = Qs[(qrow + 8) * APAD + kk + tig + 4];
#pragma unroll
            for (int nt = 0; nt < 8; nt++) {
                uint32_t b0 = Ks[(nt * 8 + gid) * APAD + kk + tig];
                uint32_t b1 = Ks[(nt * 8 + gid) * APAD + kk + tig + 4];
                mma_tf32(s[nt][0], s[nt][1], s[nt][2], s[nt][3],
                         a0, a1, a2, a3, b0, b1);
            }
        }

        // ---- scale to log2 domain + causal mask + per-thread max
        float pm0 = -1e30f, pm1 = -1e30f;
        if (kt == qt) {
            int q0l = qrow, q1l = qrow + 8;
#pragma unroll
            for (int nt = 0; nt < 8; nt++) {
                int k0 = nt * 8 + 2 * tig;
                s[nt][0] = (k0     <= q0l) ? s[nt][0] * SC : -1e30f;
                s[nt][1] = (k0 + 1 <= q0l) ? s[nt][1] * SC : -1e30f;
                s[nt][2] = (k0     <= q1l) ? s[nt][2] * SC : -1e30f;
                s[nt][3] = (k0 + 1 <= q1l) ? s[nt][3] * SC : -1e30f;
                pm0 = fmaxf(pm0, fmaxf(s[nt][0], s[nt][1]));
                pm1 = fmaxf(pm1, fmaxf(s[nt][2], s[nt][3]));
            }
        } else {
#pragma unroll
            for (int nt = 0; nt < 8; nt++) {
                s[nt][0] *= SC; s[nt][1] *= SC; s[nt][2] *= SC; s[nt][3] *= SC;
                pm0 = fmaxf(pm0, fmaxf(s[nt][0], s[nt][1]));
                pm1 = fmaxf(pm1, fmaxf(s[nt][2], s[nt][3]));
            }
        }
        // quad reduce (lanes 4g..4g+3 share q rows)
        pm0 = fmaxf(pm0, __shfl_xor_sync(0xffffffffu, pm0, 1));
        pm0 = fmaxf(pm0, __shfl_xor_sync(0xffffffffu, pm0, 2));
        pm1 = fmaxf(pm1, __shfl_xor_sync(0xffffffffu, pm1, 1));
        pm1 = fmaxf(pm1, __shfl_xor_sync(0xffffffffu, pm1, 2));

        float m_new0 = fmaxf(m_run0, pm0);
        float m_new1 = fmaxf(m_run1, pm1);
        float alpha0 = exp2p(m_run0 - m_new0);
        float alpha1 = exp2p(m_run1 - m_new1);
        m_run0 = m_new0; m_run1 = m_new1;

        // ---- p = 2^(s-m), row sums, write P^T operand (Ps[q][k], tf32)
        float ls0 = 0.f, ls1 = 0.f;
#pragma unroll
        for (int nt = 0; nt < 8; nt++) {
            float p0 = exp2p(s[nt][0] - m_new0);
            float p1 = exp2p(s[nt][1] - m_new0);
            float p2 = exp2p(s[nt][2] - m_new1);
            float p3 = exp2p(s[nt][3] - m_new1);
            ls0 += p0 + p1;
            ls1 += p2 + p3;
            int col = nt * 8 + 2 * tig;
            *(uint2*)&Ps[qrow * APAD + col] = make_uint2(f2tf32(p0), f2tf32(p1));
            *(uint2*)&Ps[(qrow + 8) * APAD + col] = make_uint2(f2tf32(p2), f2tf32(p3));
        }
        ls0 += __shfl_xor_sync(0xffffffffu, ls0, 1);
        ls0 += __shfl_xor_sync(0xffffffffu, ls0, 2);
        ls1 += __shfl_xor_sync(0xffffffffu, ls1, 1);
        ls1 += __shfl_xor_sync(0xffffffffu, ls1, 2);
        l_run0 = l_run0 * alpha0 + ls0;
        l_run1 = l_run1 * alpha1 + ls1;

        if (tig == 0) {
            alpha_sm[qrow] = alpha0;
            alpha_sm[qrow + 8] = alpha1;
        }
        __syncwarp();

        // ---- rescale O^T by alpha(q) then accumulate PV
#pragma unroll
        for (int nq = 0; nq < 2; nq++) {
            int qc = wid * 16 + nq * 8 + 2 * tig;
            float a_even = alpha_sm[qc];
            float a_odd  = alpha_sm[qc + 1];
#pragma unroll
            for (int mt = 0; mt < 4; mt++) {
                o[mt][nq][0] *= a_even;
                o[mt][nq][1] *= a_odd;
                o[mt][nq][2] *= a_even;
                o[mt][nq][3] *= a_odd;
            }
        }

#pragma unroll
        for (int kk = 0; kk < 64; kk += 8) {
            uint32_t av[4][4];
#pragma unroll
            for (int mt = 0; mt < 4; mt++) {
                int dc = mt * 16 + gid;
                av[mt][0] = Vs[(kk + tig) * VPAD + dc];
                av[mt][1] = Vs[(kk + tig) * VPAD + dc + 8];
                av[mt][2] = Vs[(kk + tig + 4) * VPAD + dc];
                av[mt][3] = Vs[(kk + tig + 4) * VPAD + dc + 8];
            }
#pragma unroll
            for (int nq = 0; nq < 2; nq++) {
                uint32_t b0 = Ps[(wid * 16 + nq * 8 + gid) * APAD + kk + tig];
                uint32_t b1 = Ps[(wid * 16 + nq * 8 + gid) * APAD + kk + tig + 4];
#pragma unroll
                for (int mt = 0; mt < 4; mt++)
                    mma_tf32(o[mt][nq][0], o[mt][nq][1], o[mt][nq][2], o[mt][nq][3],
                             av[mt][0], av[mt][1], av[mt][2], av[mt][3], b0, b1);
            }
        }
    }

    // ---- normalize + stage (reuse Qs as float buffer) + coalesced store
    if (tig == 0) {
        linv_sm[wid * 16 + gid] = 1.f / l_run0;
        linv_sm[wid * 16 + gid + 8] = 1.f / l_run1;
    }
    __syncwarp();

    float* Osm = (float*)Qs;   // [64][APAD]
#pragma unroll
    for (int nq = 0; nq < 2; nq++) {
        int qc = wid * 16 + nq * 8 + 2 * tig;
        float il_even = linv_sm[qc];
        float il_odd  = linv_sm[qc + 1];
#pragma unroll
        for (int mt = 0; mt < 4; mt++) {
            int dc = mt * 16 + gid;
            Osm[qc * APAD + dc]             = o[mt][nq][0] * il_even;
            Osm[(qc + 1) * APAD + dc]       = o[mt][nq][1] * il_odd;
            Osm[qc * APAD + dc + 8]         = o[mt][nq][2] * il_even;
            Osm[(qc + 1) * APAD + dc + 8]   = o[mt][nq][3] * il_odd;
        }
    }
    __syncthreads();

    float* Cp = ctx + ((size_t)b * S_ + qt * 64) * HD_ + h * D_;
    for (int i = tid; i < 64 * 64; i += 128)
        Cp[(i >> 6) * HD_ + (i & 63)] = Osm[(i >> 6) * APAD + (i & 63)];
}

// ---------------------------------------------------------------------------
extern "C" void kernel_launch(void* const* d_in, const int* in_sizes, int n_in,
                              void* d_out, int out_size)
{
    const float* x    = (const float*)d_in[0];
    // d_in[1] = mask (causal; handled analytically)
    const float* cosp = (const float*)d_in[2];
    const float* sinp = (const float*)d_in[3];
    const float* Wq   = (const float*)d_in[4];
    const float* Wk   = (const float*)d_in[5];
    const float* Wv   = (const float*)d_in[6];
    const float* Wo   = (const float*)d_in[7];
    const float* qsc  = (const float*)d_in[8];
    const float* ksc  = (const float*)d_in[9];

    float* out = (float*)d_out;
    float* k_out = out + (size_t)B_ * S_ * DIN_;          // [B,G,S,D]
    float* v_out = k_out + (size_t)B_ * G_ * S_ * D_;     // [B,G,S,D]

    float *q_raw, *k_raw, *v_raw, *q_att, *ctx;
    cudaGetSymbolAddress((void**)&q_raw, g_q_raw);
    cudaGetSymbolAddress((void**)&k_raw, g_k_raw);
    cudaGetSymbolAddress((void**)&v_raw, g_v_raw);
    cudaGetSymbolAddress((void**)&q_att, g_q_att);
    cudaGetSymbolAddress((void**)&ctx,   g_ctx);

    const int M = B_ * S_;  // 4096

    // QKV projections (tf32 tensor cores)
    tf32_gemm_kernel<<<dim3(HD_ / TN, M / TM), 256>>>(x, Wq, q_raw, M, HD_, DIN_);
    tf32_gemm_kernel<<<dim3(GD_ / TN, M / TM), 256>>>(x, Wk, k_raw, M, GD_, DIN_);
    tf32_gemm_kernel<<<dim3(GD_ / TN, M / TM), 256>>>(x, Wv, v_raw, M, GD_, DIN_);

    // RMSNorm + RoPE (q -> scratch [B,H,S,D]; k -> output slot [B,G,S,D])
    normrope_kernel<<<(B_ * S_ * H_) / 4, 128>>>(q_raw, q_att, qsc, cosp, sinp, H_);
    normrope_kernel<<<(B_ * S_ * G_) / 4, 128>>>(k_raw, k_out, ksc, cosp, sinp, G_);

    // v -> output slot [B,G,S,D]
    vtrans_kernel<<<(B_ * S_ * GD_) / 256, 256>>>(v_raw, v_out);

    // Tensor-core attention
    cudaFuncSetAttribute(attn_tc_kernel, cudaFuncAttributeMaxDynamicSharedMemorySize,
                         SMEM_ATC);
    attn_tc_kernel<<<dim3(S_ / 64, H_, B_), 128, SMEM_ATC>>>(q_att, k_out, v_out, ctx);

    // Output projection (tf32 tensor cores)
    tf32_gemm_kernel<<<dim3(DIN_ / TN, M / TM), 256>>>(ctx, Wo, out, M, DIN_, DIN_);
}

// round 10
// speedup vs baseline: 4.0773x; 1.2494x over previous
#include <cuda_runtime.h>
#include <cuda_bf16.h>
#include <cstdint>

#define B_ 2
#define S_ 2048
#define DIN_ 2048
#define H_ 32
#define G_ 8
#define D_ 64
#define GS_ (H_ / G_)
#define HD_ (H_ * D_)
#define GD_ (G_ * D_)

// Scratch (static device globals; allocation APIs are forbidden)
__device__ float g_q_raw[B_ * S_ * HD_];   // [B*S, H*D]
__device__ float g_k_raw[B_ * S_ * GD_];   // [B*S, G*D]
__device__ float g_v_raw[B_ * S_ * GD_];   // [B*S, G*D]
__device__ float g_q_att[B_ * S_ * HD_];   // [B, H, S, D]
__device__ float g_ctx[B_ * S_ * HD_];     // [B, S, H*D], tf32-rounded
// tf32-pre-rounded operands (cp.async path cannot convert in flight)
__device__ float g_xr[B_ * S_ * DIN_];
__device__ float g_wq[DIN_ * HD_];
__device__ float g_wk[DIN_ * GD_];
__device__ float g_wv[DIN_ * GD_];
__device__ float g_wo[HD_ * DIN_];

// ---------------------------------------------------------------------------
// Helpers
// ---------------------------------------------------------------------------
__device__ __forceinline__ uint32_t f2tf32(float f) {
    uint32_t r;
    asm("cvt.rna.tf32.f32 %0, %1;" : "=r"(r) : "f"(f));
    return r;
}

__device__ __forceinline__ void mma_tf32(
    float& c0, float& c1, float& c2, float& c3,
    uint32_t a0, uint32_t a1, uint32_t a2, uint32_t a3,
    uint32_t b0, uint32_t b1)
{
    asm volatile(
        "mma.sync.aligned.m16n8k8.row.col.f32.tf32.tf32.f32 "
        "{%0,%1,%2,%3}, {%4,%5,%6,%7}, {%8,%9}, {%0,%1,%2,%3};"
        : "+f"(c0), "+f"(c1), "+f"(c2), "+f"(c3)
        : "r"(a0), "r"(a1), "r"(a2), "r"(a3), "r"(b0), "r"(b1));
}

__device__ __forceinline__ void cp16(uint32_t smem, const void* g) {
    asm volatile("cp.async.cg.shared.global [%0], [%1], 16;" :: "r"(smem), "l"(g));
}
#define CP_COMMIT()  asm volatile("cp.async.commit_group;")
#define CP_WAIT1()   asm volatile("cp.async.wait_group 1;")

// exp2 on FMA/ALU pipes (MUFU stays idle). Rel err ~2.4e-6.
__device__ __forceinline__ float exp2p(float z) {
    z = fmaxf(z, -125.0f);
    float n = rintf(z);
    float t = (z - n) * 0.6931471805599453f;
    float p = 1.0f + t * (1.0f + t * (0.5f + t * (0.16666667f +
              t * (0.041666668f + t * 0.008333334f))));
    int ni = (int)n;
    return p * __int_as_float((ni + 127) << 23);
}

// ---------------------------------------------------------------------------
// tf32 pre-round pass (cvt.rna once per element; feeds cp.async GEMMs)
// ---------------------------------------------------------------------------
__global__ void round_tf32_kernel(const float* __restrict__ in,
                                  float* __restrict__ out, int n4)
{
    int i = blockIdx.x * blockDim.x + threadIdx.x;
    if (i < n4) {
        float4 v = ((const float4*)in)[i];
        uint4 r = make_uint4(f2tf32(v.x), f2tf32(v.y), f2tf32(v.z), f2tf32(v.w));
        ((uint4*)out)[i] = r;
    }
}

// ---------------------------------------------------------------------------
// TF32 GEMM, cp.async 3-stage pipeline. C[M,N] = A[M,K] @ B[K,N].
// Inputs must already be tf32-rounded fp32. 128x128 tile, TK=16, 256 thr.
// ---------------------------------------------------------------------------
#define TK 16
#define PA 20     // A row pad (floats): conflict-free frags + 80B (16B-aligned) rows
#define PB 136    // B row pad (floats): conflict-free frags + 544B rows
#define STG 3
#define SMEM_GEMM (STG * (128 * PA + TK * PB) * 4)

__global__ __launch_bounds__(256) void tf32_gemm_async(
    const float* __restrict__ A, const float* __restrict__ Bm,
    float* __restrict__ C, int M, int N, int K)
{
    extern __shared__ uint32_t sh[];
    const int ASTRIDE = 128 * PA;
    const int BSTRIDE = TK * PB;
    uint32_t* Bsh = sh + STG * ASTRIDE;

    int tid = threadIdx.x;
    int lane = tid & 31;
    int wid = tid >> 5;
    int gid = lane >> 2;
    int tig = lane & 3;
    int wm = (wid >> 2) * 64;
    int wn = (wid & 3) * 32;
    int m0 = blockIdx.y * 128;
    int n0 = blockIdx.x * 128;

    // cp.async mappings: 2 A-chunks + 2 B-chunks (16B) per thread per stage
    int ar = tid >> 2;            // A rows 0..63 (+64 for 2nd chunk)
    int ac = (tid & 3) * 4;       // A col offset 0/4/8/12
    int br = tid >> 5;            // B rows 0..7 (+8 for 2nd chunk)
    int bc = (tid & 31) * 4;      // B col offset 0..124

    const float* Ap = A + (size_t)m0 * K;
    const float* Bp = Bm + n0;

    uint32_t sbase;
    {
        void* p = sh;
        sbase = (uint32_t)__cvta_generic_to_shared(p);
    }
    uint32_t bbase = sbase + STG * ASTRIDE * 4;

    auto issue = [&](int s, int k0) {
        uint32_t asm0 = sbase + (s * ASTRIDE + ar * PA + ac) * 4;
        cp16(asm0, Ap + (size_t)ar * K + k0 + ac);
        cp16(asm0 + 64 * PA * 4, Ap + (size_t)(ar + 64) * K + k0 + ac);
        uint32_t bsm0 = bbase + (s * BSTRIDE + br * PB + bc) * 4;
        cp16(bsm0, Bp + (size_t)(k0 + br) * N + bc);
        cp16(bsm0 + 8 * PB * 4, Bp + (size_t)(k0 + br + 8) * N + bc);
    };

    float acc[4][4][4];
#pragma unroll
    for (int i = 0; i < 4; i++)
#pragma unroll
        for (int j = 0; j < 4; j++)
#pragma unroll
            for (int r = 0; r < 4; r++) acc[i][j][r] = 0.f;

    issue(0, 0);
    CP_COMMIT();
    issue(1, TK);
    CP_COMMIT();

    const int NIT = K / TK;
    int cur = 0;
    for (int it = 0; it < NIT; it++) {
        CP_WAIT1();
        __syncthreads();

        const uint32_t* Astg = sh + cur * ASTRIDE;
        const uint32_t* Bstg = Bsh + cur * BSTRIDE;

#pragma unroll
        for (int ks = 0; ks < TK; ks += 8) {
            uint32_t af[4][4];
#pragma unroll
            for (int mf = 0; mf < 4; mf++) {
                int mr = wm + mf * 16 + gid;
                af[mf][0] = Astg[mr * PA + ks + tig];
                af[mf][1] = Astg[(mr + 8) * PA + ks + tig];
                af[mf][2] = Astg[mr * PA + ks + tig + 4];
                af[mf][3] = Astg[(mr + 8) * PA + ks + tig + 4];
            }
            uint32_t bf[4][2];
#pragma unroll
            for (int nf = 0; nf < 4; nf++) {
                int nc = wn + nf * 8 + gid;
                bf[nf][0] = Bstg[(ks + tig) * PB + nc];
                bf[nf][1] = Bstg[(ks + tig + 4) * PB + nc];
            }
#pragma unroll
            for (int mf = 0; mf < 4; mf++)
#pragma unroll
                for (int nf = 0; nf < 4; nf++)
                    mma_tf32(acc[mf][nf][0], acc[mf][nf][1], acc[mf][nf][2], acc[mf][nf][3],
                             af[mf][0], af[mf][1], af[mf][2], af[mf][3],
                             bf[nf][0], bf[nf][1]);
        }

        __syncthreads();   // all warps done reading stage before it is overwritten
        int kn = (it + 2) * TK;
        if (kn < K) issue((it + 2) % STG, kn);
        CP_COMMIT();
        cur = (cur + 1) % STG;
    }

#pragma unroll
    for (int mf = 0; mf < 4; mf++) {
#pragma unroll
        for (int nf = 0; nf < 4; nf++) {
            int row = m0 + wm + mf * 16 + gid;
            int col = n0 + wn + nf * 8 + 2 * tig;
            *(float2*)&C[(size_t)row * N + col] =
                make_float2(acc[mf][nf][0], acc[mf][nf][1]);
            *(float2*)&C[(size_t)(row + 8) * N + col] =
                make_float2(acc[mf][nf][2], acc[mf][nf][3]);
        }
    }
}

// ---------------------------------------------------------------------------
// RMSNorm + RoPE (unchanged)
// ---------------------------------------------------------------------------
__global__ void normrope_kernel(const float* __restrict__ in,
                                float* __restrict__ out,
                                const float* __restrict__ scale,
                                const float* __restrict__ cosp,
                                const float* __restrict__ sinp,
                                int NH)
{
    int w = (blockIdx.x * blockDim.x + threadIdx.x) >> 5;
    int lane = threadIdx.x & 31;
    int nh = w % NH;
    int bs = w / NH;
    int s = bs % S_;
    int b = bs / S_;

    const float* row = in + (size_t)bs * NH * D_ + nh * D_;
    float x0 = row[lane];
    float x1 = row[lane + 32];
    float ss = x0 * x0 + x1 * x1;
#pragma unroll
    for (int o = 16; o > 0; o >>= 1) ss += __shfl_xor_sync(0xffffffffu, ss, o);
    float rinv = rsqrtf(ss * (1.0f / 64.0f) + 1e-6f);
    float n0 = x0 * rinv * scale[lane];
    float n1 = x1 * rinv * scale[lane + 32];

    float c0 = cosp[s * D_ + lane];
    float c1 = cosp[s * D_ + lane + 32];
    float s0 = sinp[s * D_ + lane];
    float s1 = sinp[s * D_ + lane + 32];
    float r0 = n0 * c0 - n1 * s0;
    float r1 = n1 * c1 + n0 * s1;

    float* orow = out + (((size_t)b * NH + nh) * S_ + s) * D_;
    orow[lane] = r0;
    orow[lane + 32] = r1;
}

// ---------------------------------------------------------------------------
// V transpose (unchanged)
// ---------------------------------------------------------------------------
__global__ void vtrans_kernel(const float* __restrict__ in, float* __restrict__ out)
{
    int i = blockIdx.x * blockDim.x + threadIdx.x;
    int d = i & 63;
    int g = (i >> 6) & 7;
    int s = (i >> 9) & 2047;
    int b = i >> 20;
    out[(((size_t)b * G_ + g) * S_ + s) * D_ + d] = in[i];
}

// ---------------------------------------------------------------------------
// Tensor-core flash attention (ctx store tf32-rounded)
// ---------------------------------------------------------------------------
#define APAD 68
#define VPAD 72
#define SMEM_ATC ((64 * APAD * 3 + 64 * VPAD + 128) * 4)

__global__ __launch_bounds__(128) void attn_tc_kernel(
    const float* __restrict__ Q, const float* __restrict__ K,
    const float* __restrict__ V, float* __restrict__ ctx)
{
    extern __shared__ uint32_t smu[];
    uint32_t* Qs = smu;
    uint32_t* Ks = Qs + 64 * APAD;
    uint32_t* Ps = Ks + 64 * APAD;
    uint32_t* Vs = Ps + 64 * APAD;
    float* alpha_sm = (float*)(Vs + 64 * VPAD);
    float* linv_sm  = alpha_sm + 64;

    int qt = (int)gridDim.x - 1 - (int)blockIdx.x;
    int h = blockIdx.y;
    int b = blockIdx.z;
    int g = h / GS_;
    int tid = threadIdx.x;
    int lane = tid & 31;
    int wid = tid >> 5;
    int gid = lane >> 2;
    int tig = lane & 3;

    const float SC = 0.125f * 1.4426950408889634f;

    const float* Qp = Q + (((size_t)b * H_ + h) * S_ + qt * 64) * D_;
    for (int i = tid; i < 64 * D_; i += 128)
        Qs[(i >> 6) * APAD + (i & 63)] = f2tf32(Qp[i]);

    float o[4][2][4];
#pragma unroll
    for (int mt = 0; mt < 4; mt++)
#pragma unroll
        for (int nq = 0; nq < 2; nq++)
#pragma unroll
            for (int r = 0; r < 4; r++) o[mt][nq][r] = 0.f;
    float m_run0 = -1e30f, m_run1 = -1e30f;
    float l_run0 = 0.f, l_run1 = 0.f;

    const float* Kbase = K + ((size_t)b * G_ + g) * S_ * D_;
    const float* Vbase = V + ((size_t)b * G_ + g) * S_ * D_;

    for (int kt = 0; kt <= qt; kt++) {
        __syncthreads();
        const float* Kp = Kbase + (size_t)kt * 64 * D_;
        const float* Vp = Vbase + (size_t)kt * 64 * D_;
        for (int i = tid; i < 64 * D_; i += 128) {
            int r = i >> 6, c = i & 63;
            Ks[r * APAD + c] = f2tf32(Kp[i]);
            Vs[r * VPAD + c] = f2tf32(Vp[i]);
        }
        __syncthreads();

        float s[8][4];
#pragma unroll
        for (int nt = 0; nt < 8; nt++)
#pragma unroll
            for (int r = 0; r < 4; r++) s[nt][r] = 0.f;

        int qrow = wid * 16 + gid;
#pragma unroll
        for (int kk = 0; kk < 64; kk += 8) {
            uint32_t a0 = Qs[qrow * APAD + kk + tig];
            uint32_t a1 = Qs[(qrow + 8) * APAD + kk + tig];
            uint32_t a2 = Qs[qrow * APAD + kk + tig + 4];
            uint32_t a3 = Qs[(qrow + 8) * APAD + kk + tig + 4];
#pragma unroll
            for (int nt = 0; nt < 8; nt++) {
                uint32_t b0 = Ks[(nt * 8 + gid) * APAD + kk + tig];
                uint32_t b1 = Ks[(nt * 8 + gid) * APAD + kk + tig + 4];
                mma_tf32(s[nt][0], s[nt][1], s[nt][2], s[nt][3],
                         a0, a1, a2, a3, b0, b1);
            }
        }

        float pm0 = -1e30f, pm1 = -1e30f;
        if (kt == qt) {
            int q0l = qrow, q1l = qrow + 8;
#pragma unroll
            for (int nt = 0; nt < 8; nt++) {
                int k0 = nt * 8 + 2 * tig;
                s[nt][0] = (k0     <= q0l) ? s[nt][0] * SC : -1e30f;
                s[nt][1] = (k0 + 1 <= q0l) ? s[nt][1] * SC : -1e30f;
                s[nt][2] = (k0     <= q1l) ? s[nt][2] * SC : -1e30f;
                s[nt][3] = (k0 + 1 <= q1l) ? s[nt][3] * SC : -1e30f;
                pm0 = fmaxf(pm0, fmaxf(s[nt][0], s[nt][1]));
                pm1 = fmaxf(pm1, fmaxf(s[nt][2], s[nt][3]));
            }
        } else {
#pragma unroll
            for (int nt = 0; nt < 8; nt++) {
                s[nt][0] *= SC; s[nt][1] *= SC; s[nt][2] *= SC; s[nt][3] *= SC;
                pm0 = fmaxf(pm0, fmaxf(s[nt][0], s[nt][1]));
                pm1 = fmaxf(pm1, fmaxf(s[nt][2], s[nt][3]));
            }
        }
        pm0 = fmaxf(pm0, __shfl_xor_sync(0xffffffffu, pm0, 1));
        pm0 = fmaxf(pm0, __shfl_xor_sync(0xffffffffu, pm0, 2));
        pm1 = fmaxf(pm1, __shfl_xor_sync(0xffffffffu, pm1, 1));
        pm1 = fmaxf(pm1, __shfl_xor_sync(0xffffffffu, pm1, 2));

        float m_new0 = fmaxf(m_run0, pm0);
        float m_new1 = fmaxf(m_run1, pm1);
        float alpha0 = exp2p(m_run0 - m_new0);
        float alpha1 = exp2p(m_run1 - m_new1);
        m_run0 = m_new0; m_run1 = m_new1;

        float ls0 = 0.f, ls1 = 0.f;
#pragma unroll
        for (int nt = 0; nt < 8; nt++) {
            float p0 = exp2p(s[nt][0] - m_new0);
            float p1 = exp2p(s[nt][1] - m_new0);
            float p2 = exp2p(s[nt][2] - m_new1);
            float p3 = exp2p(s[nt][3] - m_new1);
            ls0 += p0 + p1;
            ls1 += p2 + p3;
            int col = nt * 8 + 2 * tig;
            *(uint2*)&Ps[qrow * APAD + col] = make_uint2(f2tf32(p0), f2tf32(p1));
            *(uint2*)&Ps[(qrow + 8) * APAD + col] = make_uint2(f2tf32(p2), f2tf32(p3));
        }
        ls0 += __shfl_xor_sync(0xffffffffu, ls0, 1);
        ls0 += __shfl_xor_sync(0xffffffffu, ls0, 2);
        ls1 += __shfl_xor_sync(0xffffffffu, ls1, 1);
        ls1 += __shfl_xor_sync(0xffffffffu, ls1, 2);
        l_run0 = l_run0 * alpha0 + ls0;
        l_run1 = l_run1 * alpha1 + ls1;

        if (tig == 0) {
            alpha_sm[qrow] = alpha0;
            alpha_sm[qrow + 8] = alpha1;
        }
        __syncwarp();

#pragma unroll
        for (int nq = 0; nq < 2; nq++) {
            int qc = wid * 16 + nq * 8 + 2 * tig;
            float a_even = alpha_sm[qc];
            float a_odd  = alpha_sm[qc + 1];
#pragma unroll
            for (int mt = 0; mt < 4; mt++) {
                o[mt][nq][0] *= a_even;
                o[mt][nq][1] *= a_odd;
                o[mt][nq][2] *= a_even;
                o[mt][nq][3] *= a_odd;
            }
        }

#pragma unroll
        for (int kk = 0; kk < 64; kk += 8) {
            uint32_t av[4][4];
#pragma unroll
            for (int mt = 0; mt < 4; mt++) {
                int dc = mt * 16 + gid;
                av[mt][0] = Vs[(kk + tig) * VPAD + dc];
                av[mt][1] = Vs[(kk + tig) * VPAD + dc + 8];
                av[mt][2] = Vs[(kk + tig + 4) * VPAD + dc];
                av[mt][3] = Vs[(kk + tig + 4) * VPAD + dc + 8];
            }
#pragma unroll
            for (int nq = 0; nq < 2; nq++) {
                uint32_t b0 = Ps[(wid * 16 + nq * 8 + gid) * APAD + kk + tig];
                uint32_t b1 = Ps[(wid * 16 + nq * 8 + gid) * APAD + kk + tig + 4];
#pragma unroll
                for (int mt = 0; mt < 4; mt++)
                    mma_tf32(o[mt][nq][0], o[mt][nq][1], o[mt][nq][2], o[mt][nq][3],
                             av[mt][0], av[mt][1], av[mt][2], av[mt][3], b0, b1);
            }
        }
    }

    if (tig == 0) {
        linv_sm[wid * 16 + gid] = 1.f / l_run0;
        linv_sm[wid * 16 + gid + 8] = 1.f / l_run1;
    }
    __syncwarp();

    float* Osm = (float*)Qs;
#pragma unroll
    for (int nq = 0; nq < 2; nq++) {
        int qc = wid * 16 + nq * 8 + 2 * tig;
        float il_even = linv_sm[qc];
        float il_odd  = linv_sm[qc + 1];
#pragma unroll
        for (int mt = 0; mt < 4; mt++) {
            int dc = mt * 16 + gid;
            Osm[qc * APAD + dc]             = o[mt][nq][0] * il_even;
            Osm[(qc + 1) * APAD + dc]       = o[mt][nq][1] * il_odd;
            Osm[qc * APAD + dc + 8]         = o[mt][nq][2] * il_even;
            Osm[(qc + 1) * APAD + dc + 8]   = o[mt][nq][3] * il_odd;
        }
    }
    __syncthreads();

    // ctx feeds the cp.async GEMM: store tf32-rounded
    float* Cp = ctx + ((size_t)b * S_ + qt * 64) * HD_ + h * D_;
    for (int i = tid; i < 64 * 64; i += 128)
        Cp[(i >> 6) * HD_ + (i & 63)] =
            __uint_as_float(f2tf32(Osm[(i >> 6) * APAD + (i & 63)]));
}

// ---------------------------------------------------------------------------
extern "C" void kernel_launch(void* const* d_in, const int* in_sizes, int n_in,
                              void* d_out, int out_size)
{
    const float* x    = (const float*)d_in[0];
    // d_in[1] = mask (causal; handled analytically)
    const float* cosp = (const float*)d_in[2];
    const float* sinp = (const float*)d_in[3];
    const float* Wq   = (const float*)d_in[4];
    const float* Wk   = (const float*)d_in[5];
    const float* Wv   = (const float*)d_in[6];
    const float* Wo   = (const float*)d_in[7];
    const float* qsc  = (const float*)d_in[8];
    const float* ksc  = (const float*)d_in[9];

    float* out = (float*)d_out;
    float* k_out = out + (size_t)B_ * S_ * DIN_;          // [B,G,S,D]
    float* v_out = k_out + (size_t)B_ * G_ * S_ * D_;     // [B,G,S,D]

    float *q_raw, *k_raw, *v_raw, *q_att, *ctx;
    float *xr, *wq, *wk, *wv, *wo;
    cudaGetSymbolAddress((void**)&q_raw, g_q_raw);
    cudaGetSymbolAddress((void**)&k_raw, g_k_raw);
    cudaGetSymbolAddress((void**)&v_raw, g_v_raw);
    cudaGetSymbolAddress((void**)&q_att, g_q_att);
    cudaGetSymbolAddress((void**)&ctx,   g_ctx);
    cudaGetSymbolAddress((void**)&xr,    g_xr);
    cudaGetSymbolAddress((void**)&wq,    g_wq);
    cudaGetSymbolAddress((void**)&wk,    g_wk);
    cudaGetSymbolAddress((void**)&wv,    g_wv);
    cudaGetSymbolAddress((void**)&wo,    g_wo);

    const int M = B_ * S_;  // 4096

    // Pre-round operands to tf32 (cvt.rna), enabling raw cp.async in GEMMs
    {
        int n4x = (M * DIN_) / 4;
        round_tf32_kernel<<<(n4x + 255) / 256, 256>>>(x, xr, n4x);
        int n4q = (DIN_ * HD_) / 4;
        round_tf32_kernel<<<(n4q + 255) / 256, 256>>>(Wq, wq, n4q);
        int n4k = (DIN_ * GD_) / 4;
        round_tf32_kernel<<<(n4k + 255) / 256, 256>>>(Wk, wk, n4k);
        round_tf32_kernel<<<(n4k + 255) / 256, 256>>>(Wv, wv, n4k);
        int n4o = (HD_ * DIN_) / 4;
        round_tf32_kernel<<<(n4o + 255) / 256, 256>>>(Wo, wo, n4o);
    }

    cudaFuncSetAttribute(tf32_gemm_async, cudaFuncAttributeMaxDynamicSharedMemorySize,
                         SMEM_GEMM);

    // QKV projections
    tf32_gemm_async<<<dim3(HD_ / 128, M / 128), 256, SMEM_GEMM>>>(xr, wq, q_raw, M, HD_, DIN_);
    tf32_gemm_async<<<dim3(GD_ / 128, M / 128), 256, SMEM_GEMM>>>(xr, wk, k_raw, M, GD_, DIN_);
    tf32_gemm_async<<<dim3(GD_ / 128, M / 128), 256, SMEM_GEMM>>>(xr, wv, v_raw, M, GD_, DIN_);

    // RMSNorm + RoPE
    normrope_kernel<<<(B_ * S_ * H_) / 4, 128>>>(q_raw, q_att, qsc, cosp, sinp, H_);
    normrope_kernel<<<(B_ * S_ * G_) / 4, 128>>>(k_raw, k_out, ksc, cosp, sinp, G_);

    // v -> output slot [B,G,S,D]
    vtrans_kernel<<<(B_ * S_ * GD_) / 256, 256>>>(v_raw, v_out);

    // Tensor-core attention (writes tf32-rounded ctx)
    cudaFuncSetAttribute(attn_tc_kernel, cudaFuncAttributeMaxDynamicSharedMemorySize,
                         SMEM_ATC);
    attn_tc_kernel<<<dim3(S_ / 64, H_, B_), 128, SMEM_ATC>>>(q_att, k_out, v_out, ctx);

    // Output projection
    tf32_gemm_async<<<dim3(DIN_ / 128, M / 128), 256, SMEM_GEMM>>>(ctx, wo, out, M, DIN_, DIN_);
}

// round 15
// speedup vs baseline: 4.1664x; 1.0218x over previous
#include <cuda_runtime.h>
#include <cuda_bf16.h>
#include <cstdint>

#define B_ 2
#define S_ 2048
#define DIN_ 2048
#define H_ 32
#define G_ 8
#define D_ 64
#define GS_ (H_ / G_)
#define HD_ (H_ * D_)
#define GD_ (G_ * D_)

// Scratch (static device globals; allocation APIs are forbidden)
__device__ float g_q_raw[B_ * S_ * HD_];   // [B*S, H*D]
__device__ float g_k_raw[B_ * S_ * GD_];   // [B*S, G*D]
__device__ float g_v_raw[B_ * S_ * GD_];   // [B*S, G*D]
__device__ float g_q_att[B_ * S_ * HD_];   // [B, H, S, D]
__device__ float g_ctx[B_ * S_ * HD_];     // [B, S, H*D], tf32-rounded
// tf32-pre-rounded operands (cp.async path cannot convert in flight)
__device__ float g_xr[B_ * S_ * DIN_];
__device__ float g_wq[DIN_ * HD_];
__device__ float g_wk[DIN_ * GD_];
__device__ float g_wv[DIN_ * GD_];
__device__ float g_wo[HD_ * DIN_];

// ---------------------------------------------------------------------------
// Helpers
// ---------------------------------------------------------------------------
__device__ __forceinline__ uint32_t f2tf32(float f) {
    uint32_t r;
    asm("cvt.rna.tf32.f32 %0, %1;" : "=r"(r) : "f"(f));
    return r;
}

__device__ __forceinline__ void mma_tf32(
    float& c0, float& c1, float& c2, float& c3,
    uint32_t a0, uint32_t a1, uint32_t a2, uint32_t a3,
    uint32_t b0, uint32_t b1)
{
    asm volatile(
        "mma.sync.aligned.m16n8k8.row.col.f32.tf32.tf32.f32 "
        "{%0,%1,%2,%3}, {%4,%5,%6,%7}, {%8,%9}, {%0,%1,%2,%3};"
        : "+f"(c0), "+f"(c1), "+f"(c2), "+f"(c3)
        : "r"(a0), "r"(a1), "r"(a2), "r"(a3), "r"(b0), "r"(b1));
}

__device__ __forceinline__ void ldsm_x4(
    uint32_t& r0, uint32_t& r1, uint32_t& r2, uint32_t& r3, uint32_t addr)
{
    asm volatile(
        "ldmatrix.sync.aligned.m8n8.x4.shared.b16 {%0,%1,%2,%3}, [%4];"
        : "=r"(r0), "=r"(r1), "=r"(r2), "=r"(r3) : "r"(addr));
}

__device__ __forceinline__ void cp16(uint32_t smem, const void* g) {
    asm volatile("cp.async.cg.shared.global [%0], [%1], 16;" :: "r"(smem), "l"(g));
}
#define CP_COMMIT()  asm volatile("cp.async.commit_group;")
#define CP_WAIT1()   asm volatile("cp.async.wait_group 1;")

// exp2 on FMA/ALU pipes (MUFU stays idle). Rel err ~2.4e-6.
__device__ __forceinline__ float exp2p(float z) {
    z = fmaxf(z, -125.0f);
    float n = rintf(z);
    float t = (z - n) * 0.6931471805599453f;
    float p = 1.0f + t * (1.0f + t * (0.5f + t * (0.16666667f +
              t * (0.041666668f + t * 0.008333334f))));
    int ni = (int)n;
    return p * __int_as_float((ni + 127) << 23);
}

// ---------------------------------------------------------------------------
// tf32 pre-round pass (cvt.rna once per element; feeds cp.async GEMMs)
// ---------------------------------------------------------------------------
__global__ void round_tf32_kernel(const float* __restrict__ in,
                                  float* __restrict__ out, int n4)
{
    int i = blockIdx.x * blockDim.x + threadIdx.x;
    if (i < n4) {
        float4 v = ((const float4*)in)[i];
        uint4 r = make_uint4(f2tf32(v.x), f2tf32(v.y), f2tf32(v.z), f2tf32(v.w));
        ((uint4*)out)[i] = r;
    }
}

// ---------------------------------------------------------------------------
// TF32 GEMM, cp.async 3-stage pipeline + ldmatrix A-fragments.
// C[M,N] = A[M,K] @ B[K,N]; inputs pre-rounded tf32. 128x128, TK=16, 256 thr.
// ---------------------------------------------------------------------------
#define TK 16
#define PA 20     // A row pad (floats): 80B rows -> LDSM phases conflict-free
#define PB 136    // B row pad (floats): conflict-free B fragments
#define STG 3
#define SMEM_GEMM (STG * (128 * PA + TK * PB) * 4)

__global__ __launch_bounds__(256) void tf32_gemm_async(
    const float* __restrict__ A, const float* __restrict__ Bm,
    float* __restrict__ C, int M, int N, int K)
{
    extern __shared__ uint32_t sh[];
    const int ASTRIDE = 128 * PA;
    const int BSTRIDE = TK * PB;
    uint32_t* Bsh = sh + STG * ASTRIDE;

    int tid = threadIdx.x;
    int lane = tid & 31;
    int wid = tid >> 5;
    int gid = lane >> 2;
    int tig = lane & 3;
    int wm = (wid >> 2) * 64;
    int wn = (wid & 3) * 32;
    int m0 = blockIdx.y * 128;
    int n0 = blockIdx.x * 128;

    // ldmatrix per-lane tile addressing: tile = lane>>3, row-in-tile = lane&7
    // tiles: 0:(rows+0,k+0) 1:(rows+8,k+0) 2:(rows+0,k+4) 3:(rows+8,k+4)
    int rowsel = ((lane >> 3) & 1) * 8 + (lane & 7);
    int colsel = (lane >> 4) * 4;

    // cp.async mappings: 2 A-chunks + 2 B-chunks (16B) per thread per stage
    int ar = tid >> 2;            // A rows 0..63 (+64 for 2nd chunk)
    int ac = (tid & 3) * 4;       // A col offset 0/4/8/12
    int br = tid >> 5;            // B rows 0..7 (+8 for 2nd chunk)
    int bc = (tid & 31) * 4;      // B col offset 0..124

    const float* Ap = A + (size_t)m0 * K;
    const float* Bp = Bm + n0;

    uint32_t sbase;
    {
        void* p = sh;
        sbase = (uint32_t)__cvta_generic_to_shared(p);
    }
    uint32_t bbase = sbase + STG * ASTRIDE * 4;

    auto issue = [&](int s, int k0) {
        uint32_t asm0 = sbase + (s * ASTRIDE + ar * PA + ac) * 4;
        cp16(asm0, Ap + (size_t)ar * K + k0 + ac);
        cp16(asm0 + 64 * PA * 4, Ap + (size_t)(ar + 64) * K + k0 + ac);
        uint32_t bsm0 = bbase + (s * BSTRIDE + br * PB + bc) * 4;
        cp16(bsm0, Bp + (size_t)(k0 + br) * N + bc);
        cp16(bsm0 + 8 * PB * 4, Bp + (size_t)(k0 + br + 8) * N + bc);
    };

    float acc[4][4][4];
#pragma unroll
    for (int i = 0; i < 4; i++)
#pragma unroll
        for (int j = 0; j < 4; j++)
#pragma unroll
            for (int r = 0; r < 4; r++) acc[i][j][r] = 0.f;

    issue(0, 0);
    CP_COMMIT();
    issue(1, TK);
    CP_COMMIT();

    const int NIT = K / TK;
    int cur = 0;
    for (int it = 0; it < NIT; it++) {
        CP_WAIT1();
        __syncthreads();

        uint32_t astage = sbase + cur * ASTRIDE * 4;
        const uint32_t* Bstg = Bsh + cur * BSTRIDE;

#pragma unroll
        for (int ks = 0; ks < TK; ks += 8) {
            uint32_t af[4][4];
#pragma unroll
            for (int mf = 0; mf < 4; mf++) {
                uint32_t addr = astage +
                    ((wm + mf * 16 + rowsel) * PA + ks + colsel) * 4;
                ldsm_x4(af[mf][0], af[mf][1], af[mf][2], af[mf][3], addr);
            }
            uint32_t bf[4][2];
#pragma unroll
            for (int nf = 0; nf < 4; nf++) {
                int nc = wn + nf * 8 + gid;
                bf[nf][0] = Bstg[(ks + tig) * PB + nc];
                bf[nf][1] = Bstg[(ks + tig + 4) * PB + nc];
            }
#pragma unroll
            for (int mf = 0; mf < 4; mf++)
#pragma unroll
                for (int nf = 0; nf < 4; nf++)
                    mma_tf32(acc[mf][nf][0], acc[mf][nf][1], acc[mf][nf][2], acc[mf][nf][3],
                             af[mf][0], af[mf][1], af[mf][2], af[mf][3],
                             bf[nf][0], bf[nf][1]);
        }

        __syncthreads();   // all warps done reading stage before it is overwritten
        int kn = (it + 2) * TK;
        if (kn < K) issue((it + 2) % STG, kn);
        CP_COMMIT();
        cur = (cur + 1) % STG;
    }

#pragma unroll
    for (int mf = 0; mf < 4; mf++) {
#pragma unroll
        for (int nf = 0; nf < 4; nf++) {
            int row = m0 + wm + mf * 16 + gid;
            int col = n0 + wn + nf * 8 + 2 * tig;
            *(float2*)&C[(size_t)row * N + col] =
                make_float2(acc[mf][nf][0], acc[mf][nf][1]);
            *(float2*)&C[(size_t)(row + 8) * N + col] =
                make_float2(acc[mf][nf][2], acc[mf][nf][3]);
        }
    }
}

// ---------------------------------------------------------------------------
// RMSNorm + RoPE (unchanged)
// ---------------------------------------------------------------------------
__global__ void normrope_kernel(const float* __restrict__ in,
                                float* __restrict__ out,
                                const float* __restrict__ scale,
                                const float* __restrict__ cosp,
                                const float* __restrict__ sinp,
                                int NH)
{
    int w = (blockIdx.x * blockDim.x + threadIdx.x) >> 5;
    int lane = threadIdx.x & 31;
    int nh = w % NH;
    int bs = w / NH;
    int s = bs % S_;
    int b = bs / S_;

    const float* row = in + (size_t)bs * NH * D_ + nh * D_;
    float x0 = row[lane];
    float x1 = row[lane + 32];
    float ss = x0 * x0 + x1 * x1;
#pragma unroll
    for (int o = 16; o > 0; o >>= 1) ss += __shfl_xor_sync(0xffffffffu, ss, o);
    float rinv = rsqrtf(ss * (1.0f / 64.0f) + 1e-6f);
    float n0 = x0 * rinv * scale[lane];
    float n1 = x1 * rinv * scale[lane + 32];

    float c0 = cosp[s * D_ + lane];
    float c1 = cosp[s * D_ + lane + 32];
    float s0 = sinp[s * D_ + lane];
    float s1 = sinp[s * D_ + lane + 32];
    float r0 = n0 * c0 - n1 * s0;
    float r1 = n1 * c1 + n0 * s1;

    float* orow = out + (((size_t)b * NH + nh) * S_ + s) * D_;
    orow[lane] = r0;
    orow[lane + 32] = r1;
}

// ---------------------------------------------------------------------------
// V transpose (unchanged)
// ---------------------------------------------------------------------------
__global__ void vtrans_kernel(const float* __restrict__ in, float* __restrict__ out)
{
    int i = blockIdx.x * blockDim.x + threadIdx.x;
    int d = i & 63;
    int g = (i >> 6) & 7;
    int s = (i >> 9) & 2047;
    int b = i >> 20;
    out[(((size_t)b * G_ + g) * S_ + s) * D_ + d] = in[i];
}

// ---------------------------------------------------------------------------
// Tensor-core flash attention (unchanged from R10)
// ---------------------------------------------------------------------------
#define APAD 68
#define VPAD 72
#define SMEM_ATC ((64 * APAD * 3 + 64 * VPAD + 128) * 4)

__global__ __launch_bounds__(128) void attn_tc_kernel(
    const float* __restrict__ Q, const float* __restrict__ K,
    const float* __restrict__ V, float* __restrict__ ctx)
{
    extern __shared__ uint32_t smu[];
    uint32_t* Qs = smu;
    uint32_t* Ks = Qs + 64 * APAD;
    uint32_t* Ps = Ks + 64 * APAD;
    uint32_t* Vs = Ps + 64 * APAD;
    float* alpha_sm = (float*)(Vs + 64 * VPAD);
    float* linv_sm  = alpha_sm + 64;

    int qt = (int)gridDim.x - 1 - (int)blockIdx.x;
    int h = blockIdx.y;
    int b = blockIdx.z;
    int g = h / GS_;
    int tid = threadIdx.x;
    int lane = tid & 31;
    int wid = tid >> 5;
    int gid = lane >> 2;
    int tig = lane & 3;

    const float SC = 0.125f * 1.4426950408889634f;

    const float* Qp = Q + (((size_t)b * H_ + h) * S_ + qt * 64) * D_;
    for (int i = tid; i < 64 * D_; i += 128)
        Qs[(i >> 6) * APAD + (i & 63)] = f2tf32(Qp[i]);

    float o[4][2][4];
#pragma unroll
    for (int mt = 0; mt < 4; mt++)
#pragma unroll
        for (int nq = 0; nq < 2; nq++)
#pragma unroll
            for (int r = 0; r < 4; r++) o[mt][nq][r] = 0.f;
    float m_run0 = -1e30f, m_run1 = -1e30f;
    float l_run0 = 0.f, l_run1 = 0.f;

    const float* Kbase = K + ((size_t)b * G_ + g) * S_ * D_;
    const float* Vbase = V + ((size_t)b * G_ + g) * S_ * D_;

    for (int kt = 0; kt <= qt; kt++) {
        __syncthreads();
        const float* Kp = Kbase + (size_t)kt * 64 * D_;
        const float* Vp = Vbase + (size_t)kt * 64 * D_;
        for (int i = tid; i < 64 * D_; i += 128) {
            int r = i >> 6, c = i & 63;
            Ks[r * APAD + c] = f2tf32(Kp[i]);
            Vs[r * VPAD + c] = f2tf32(Vp[i]);
        }
        __syncthreads();

        float s[8][4];
#pragma unroll
        for (int nt = 0; nt < 8; nt++)
#pragma unroll
            for (int r = 0; r < 4; r++) s[nt][r] = 0.f;

        int qrow = wid * 16 + gid;
#pragma unroll
        for (int kk = 0; kk < 64; kk += 8) {
            uint32_t a0 = Qs[qrow * APAD + kk + tig];
            uint32_t a1 = Qs[(qrow + 8) * APAD + kk + tig];
            uint32_t a2 = Qs[qrow * APAD + kk + tig + 4];
            uint32_t a3 = Qs[(qrow + 8) * APAD + kk + tig + 4];
#pragma unroll
            for (int nt = 0; nt < 8; nt++) {
                uint32_t b0 = Ks[(nt * 8 + gid) * APAD + kk + tig];
                uint32_t b1 = Ks[(nt * 8 + gid) * APAD + kk + tig + 4];
                mma_tf32(s[nt][0], s[nt][1], s[nt][2], s[nt][3],
                         a0, a1, a2, a3, b0, b1);
            }
        }

        float pm0 = -1e30f, pm1 = -1e30f;
        if (kt == qt) {
            int q0l = qrow, q1l = qrow + 8;
#pragma unroll
            for (int nt = 0; nt < 8; nt++) {
                int k0 = nt * 8 + 2 * tig;
                s[nt][0] = (k0     <= q0l) ? s[nt][0] * SC : -1e30f;
                s[nt][1] = (k0 + 1 <= q0l) ? s[nt][1] * SC : -1e30f;
                s[nt][2] = (k0     <= q1l) ? s[nt][2] * SC : -1e30f;
                s[nt][3] = (k0 + 1 <= q1l) ? s[nt][3] * SC : -1e30f;
                pm0 = fmaxf(pm0, fmaxf(s[nt][0], s[nt][1]));
                pm1 = fmaxf(pm1, fmaxf(s[nt][2], s[nt][3]));
            }
        } else {
#pragma unroll
            for (int nt = 0; nt < 8; nt++) {
                s[nt][0] *= SC; s[nt][1] *= SC; s[nt][2] *= SC; s[nt][3] *= SC;
                pm0 = fmaxf(pm0, fmaxf(s[nt][0], s[nt][1]));
                pm1 = fmaxf(pm1, fmaxf(s[nt][2], s[nt][3]));
            }
        }
        pm0 = fmaxf(pm0, __shfl_xor_sync(0xffffffffu, pm0, 1));
        pm0 = fmaxf(pm0, __shfl_xor_sync(0xffffffffu, pm0, 2));
        pm1 = fmaxf(pm1, __shfl_xor_sync(0xffffffffu, pm1, 1));
        pm1 = fmaxf(pm1, __shfl_xor_sync(0xffffffffu, pm1, 2));

        float m_new0 = fmaxf(m_run0, pm0);
        float m_new1 = fmaxf(m_run1, pm1);
        float alpha0 = exp2p(m_run0 - m_new0);
        float alpha1 = exp2p(m_run1 - m_new1);
        m_run0 = m_new0; m_run1 = m_new1;

        float ls0 = 0.f, ls1 = 0.f;
#pragma unroll
        for (int nt = 0; nt < 8; nt++) {
            float p0 = exp2p(s[nt][0] - m_new0);
            float p1 = exp2p(s[nt][1] - m_new0);
            float p2 = exp2p(s[nt][2] - m_new1);
            float p3 = exp2p(s[nt][3] - m_new1);
            ls0 += p0 + p1;
            ls1 += p2 + p3;
            int col = nt * 8 + 2 * tig;
            *(uint2*)&Ps[qrow * APAD + col] = make_uint2(f2tf32(p0), f2tf32(p1));
            *(uint2*)&Ps[(qrow + 8) * APAD + col] = make_uint2(f2tf32(p2), f2tf32(p3));
        }
        ls0 += __shfl_xor_sync(0xffffffffu, ls0, 1);
        ls0 += __shfl_xor_sync(0xffffffffu, ls0, 2);
        ls1 += __shfl_xor_sync(0xffffffffu, ls1, 1);
        ls1 += __shfl_xor_sync(0xffffffffu, ls1, 2);
        l_run0 = l_run0 * alpha0 + ls0;
        l_run1 = l_run1 * alpha1 + ls1;

        if (tig == 0) {
            alpha_sm[qrow] = alpha0;
            alpha_sm[qrow + 8] = alpha1;
        }
        __syncwarp();

#pragma unroll
        for (int nq = 0; nq < 2; nq++) {
            int qc = wid * 16 + nq * 8 + 2 * tig;
            float a_even = alpha_sm[qc];
            float a_odd  = alpha_sm[qc + 1];
#pragma unroll
            for (int mt = 0; mt < 4; mt++) {
                o[mt][nq][0] *= a_even;
                o[mt][nq][1] *= a_odd;
                o[mt][nq][2] *= a_even;
                o[mt][nq][3] *= a_odd;
            }
        }

#pragma unroll
        for (int kk = 0; kk < 64; kk += 8) {
            uint32_t av[4][4];
#pragma unroll
            for (int mt = 0; mt < 4; mt++) {
                int dc = mt * 16 + gid;
                av[mt][0] = Vs[(kk + tig) * VPAD + dc];
                av[mt][1] = Vs[(kk + tig) * VPAD + dc + 8];
                av[mt][2] = Vs[(kk + tig + 4) * VPAD + dc];
                av[mt][3] = Vs[(kk + tig + 4) * VPAD + dc + 8];
            }
#pragma unroll
            for (int nq = 0; nq < 2; nq++) {
                uint32_t b0 = Ps[(wid * 16 + nq * 8 + gid) * APAD + kk + tig];
                uint32_t b1 = Ps[(wid * 16 + nq * 8 + gid) * APAD + kk + tig + 4];
#pragma unroll
                for (int mt = 0; mt < 4; mt++)
                    mma_tf32(o[mt][nq][0], o[mt][nq][1], o[mt][nq][2], o[mt][nq][3],
                             av[mt][0], av[mt][1], av[mt][2], av[mt][3], b0, b1);
            }
        }
    }

    if (tig == 0) {
        linv_sm[wid * 16 + gid] = 1.f / l_run0;
        linv_sm[wid * 16 + gid + 8] = 1.f / l_run1;
    }
    __syncwarp();

    float* Osm = (float*)Qs;
#pragma unroll
    for (int nq = 0; nq < 2; nq++) {
        int qc = wid * 16 + nq * 8 + 2 * tig;
        float il_even = linv_sm[qc];
        float il_odd  = linv_sm[qc + 1];
#pragma unroll
        for (int mt = 0; mt < 4; mt++) {
            int dc = mt * 16 + gid;
            Osm[qc * APAD + dc]             = o[mt][nq][0] * il_even;
            Osm[(qc + 1) * APAD + dc]       = o[mt][nq][1] * il_odd;
            Osm[qc * APAD + dc + 8]         = o[mt][nq][2] * il_even;
            Osm[(qc + 1) * APAD + dc + 8]   = o[mt][nq][3] * il_odd;
        }
    }
    __syncthreads();

    // ctx feeds the cp.async GEMM: store tf32-rounded
    float* Cp = ctx + ((size_t)b * S_ + qt * 64) * HD_ + h * D_;
    for (int i = tid; i < 64 * 64; i += 128)
        Cp[(i >> 6) * HD_ + (i & 63)] =
            __uint_as_float(f2tf32(Osm[(i >> 6) * APAD + (i & 63)]));
}

// ---------------------------------------------------------------------------
extern "C" void kernel_launch(void* const* d_in, const int* in_sizes, int n_in,
                              void* d_out, int out_size)
{
    const float* x    = (const float*)d_in[0];
    // d_in[1] = mask (causal; handled analytically)
    const float* cosp = (const float*)d_in[2];
    const float* sinp = (const float*)d_in[3];
    const float* Wq   = (const float*)d_in[4];
    const float* Wk   = (const float*)d_in[5];
    const float* Wv   = (const float*)d_in[6];
    const float* Wo   = (const float*)d_in[7];
    const float* qsc  = (const float*)d_in[8];
    const float* ksc  = (const float*)d_in[9];

    float* out = (float*)d_out;
    float* k_out = out + (size_t)B_ * S_ * DIN_;          // [B,G,S,D]
    float* v_out = k_out + (size_t)B_ * G_ * S_ * D_;     // [B,G,S,D]

    float *q_raw, *k_raw, *v_raw, *q_att, *ctx;
    float *xr, *wq, *wk, *wv, *wo;
    cudaGetSymbolAddress((void**)&q_raw, g_q_raw);
    cudaGetSymbolAddress((void**)&k_raw, g_k_raw);
    cudaGetSymbolAddress((void**)&v_raw, g_v_raw);
    cudaGetSymbolAddress((void**)&q_att, g_q_att);
    cudaGetSymbolAddress((void**)&ctx,   g_ctx);
    cudaGetSymbolAddress((void**)&xr,    g_xr);
    cudaGetSymbolAddress((void**)&wq,    g_wq);
    cudaGetSymbolAddress((void**)&wk,    g_wk);
    cudaGetSymbolAddress((void**)&wv,    g_wv);
    cudaGetSymbolAddress((void**)&wo,    g_wo);

    const int M = B_ * S_;  // 4096

    // Pre-round operands to tf32 (cvt.rna), enabling raw cp.async in GEMMs
    {
        int n4x = (M * DIN_) / 4;
        round_tf32_kernel<<<(n4x + 255) / 256, 256>>>(x, xr, n4x);
        int n4q = (DIN_ * HD_) / 4;
        round_tf32_kernel<<<(n4q + 255) / 256, 256>>>(Wq, wq, n4q);
        int n4k = (DIN_ * GD_) / 4;
        round_tf32_kernel<<<(n4k + 255) / 256, 256>>>(Wk, wk, n4k);
        round_tf32_kernel<<<(n4k + 255) / 256, 256>>>(Wv, wv, n4k);
        int n4o = (HD_ * DIN_) / 4;
        round_tf32_kernel<<<(n4o + 255) / 256, 256>>>(Wo, wo, n4o);
    }

    cudaFuncSetAttribute(tf32_gemm_async, cudaFuncAttributeMaxDynamicSharedMemorySize,
                         SMEM_GEMM);

    // QKV projections
    tf32_gemm_async<<<dim3(HD_ / 128, M / 128), 256, SMEM_GEMM>>>(xr, wq, q_raw, M, HD_, DIN_);
    tf32_gemm_async<<<dim3(GD_ / 128, M / 128), 256, SMEM_GEMM>>>(xr, wk, k_raw, M, GD_, DIN_);
    tf32_gemm_async<<<dim3(GD_ / 128, M / 128), 256, SMEM_GEMM>>>(xr, wv, v_raw, M, GD_, DIN_);

    // RMSNorm + RoPE
    normrope_kernel<<<(B_ * S_ * H_) / 4, 128>>>(q_raw, q_att, qsc, cosp, sinp, H_);
    normrope_kernel<<<(B_ * S_ * G_) / 4, 128>>>(k_raw, k_out, ksc, cosp, sinp, G_);

    // v -> output slot [B,G,S,D]
    vtrans_kernel<<<(B_ * S_ * GD_) / 256, 256>>>(v_raw, v_out);

    // Tensor-core attention (writes tf32-rounded ctx)
    cudaFuncSetAttribute(attn_tc_kernel, cudaFuncAttributeMaxDynamicSharedMemorySize,
                         SMEM_ATC);
    attn_tc_kernel<<<dim3(S_ / 64, H_, B_), 128, SMEM_ATC>>>(q_att, k_out, v_out, ctx);

    // Output projection
    tf32_gemm_async<<<dim3(DIN_ / 128, M / 128), 256, SMEM_GEMM>>>(ctx, wo, out, M, DIN_, DIN_);
}